// round 8
// baseline (speedup 1.0000x reference)
#include <cuda_runtime.h>
#include <cuda_fp16.h>
#include <math.h>
#include <stdint.h>

#define BB 2
#define SS 2048
#define DD 1024
#define HH 16
#define DHD 64
#define DFF 4096
#define NROWS (BB * SS)
#define NQKV 3072

// ---------------- scratch (device globals; no allocation) ----------------
__device__ __half g_ln[NROWS * DD];
__device__ __half g_qkv[NROWS * NQKV];
__device__ __half g_attn[NROWS * DD];
__device__ float  g_h1[NROWS * DD];
__device__ __half g_f1[NROWS * DFF];
__device__ __half g_wqkv[DD * NQKV];
__device__ float  g_bqkv[NQKV];
__device__ __half g_wo[DD * DD];
__device__ __half g_w1[DD * DFF];
__device__ __half g_w2[DFF * DD];

// ---------------- helpers --------------------------------------------------
__device__ __forceinline__ uint32_t smem_u32(const void* p) {
    uint32_t a;
    asm("{ .reg .u64 t; cvta.to.shared.u64 t, %1; cvt.u32.u64 %0, t; }" : "=r"(a) : "l"(p));
    return a;
}
__device__ __forceinline__ void cp16(void* dst_smem, const void* src) {
    uint32_t d;
    asm("{ .reg .u64 t; cvta.to.shared.u64 t, %1; cvt.u32.u64 %0, t; }"
        : "=r"(d) : "l"(dst_smem));
    asm volatile("cp.async.cg.shared.global [%0], [%1], 16;" :: "r"(d), "l"(src));
}
__device__ __forceinline__ void cp_commit() {
    asm volatile("cp.async.commit_group;");
}
template <int N>
__device__ __forceinline__ void cp_wait() {
    asm volatile("cp.async.wait_group %0;" :: "n"(N));
}
__device__ __forceinline__ void ldm_x4(uint32_t r[4], uint32_t addr) {
    asm volatile("ldmatrix.sync.aligned.m8n8.x4.shared.b16 {%0,%1,%2,%3}, [%4];"
        : "=r"(r[0]), "=r"(r[1]), "=r"(r[2]), "=r"(r[3]) : "r"(addr));
}
__device__ __forceinline__ void ldm_x4t(uint32_t r[4], uint32_t addr) {
    asm volatile("ldmatrix.sync.aligned.m8n8.x4.trans.shared.b16 {%0,%1,%2,%3}, [%4];"
        : "=r"(r[0]), "=r"(r[1]), "=r"(r[2]), "=r"(r[3]) : "r"(addr));
}
__device__ __forceinline__ void mma16(float c[4], const uint32_t a[4], const uint32_t b[2]) {
    asm volatile(
        "mma.sync.aligned.m16n8k16.row.col.f32.f16.f16.f32 "
        "{%0,%1,%2,%3}, {%4,%5,%6,%7}, {%8,%9}, {%0,%1,%2,%3};"
        : "+f"(c[0]), "+f"(c[1]), "+f"(c[2]), "+f"(c[3])
        : "r"(a[0]), "r"(a[1]), "r"(a[2]), "r"(a[3]), "r"(b[0]), "r"(b[1]));
}
__device__ __forceinline__ uint32_t packh2(float lo, float hi) {
    __half2 h = __floats2half2_rn(lo, hi);
    return *(uint32_t*)&h;
}
__device__ __forceinline__ float ex2f(float x) {
    float r;
    asm("ex2.approx.f32 %0, %1;" : "=f"(r) : "f"(x));
    return r;
}
__device__ __forceinline__ float gelu_tanh_f(float h) {
    const float c = 0.7978845608028654f;
    float u = c * (h + 0.044715f * h * h * h);
    return 0.5f * h * (1.0f + tanhf(u));
}

// ---------------- ONE fused pack kernel (all weights + biases) -------------
#define NW (DD * DD / 4)
#define NF (DD * DFF / 4)
__global__ void __launch_bounds__(256) pack_all(
    const float* __restrict__ wq, const float* __restrict__ wk,
    const float* __restrict__ wv, const float* __restrict__ wo,
    const float* __restrict__ w1, const float* __restrict__ w2,
    const float* __restrict__ bq, const float* __restrict__ bk,
    const float* __restrict__ bv,
    __half* __restrict__ wqkv, __half* __restrict__ woh,
    __half* __restrict__ w1h, __half* __restrict__ w2h,
    float* __restrict__ bqkv)
{
    long i = (long)blockIdx.x * 256 + threadIdx.x;
    if (i < 3L * NW) {
        const float* src = (i < NW) ? wq : (i < 2L * NW) ? wk : wv;
        int coff = (i < NW) ? 0 : (i < 2L * NW) ? DD : 2 * DD;
        long ii = i % NW;
        int row = (int)(ii >> 8), c4 = ((int)ii & 255) << 2;
        float4 v = ((const float4*)src)[ii];
        __half2* o = (__half2*)(wqkv + (size_t)row * NQKV + coff + c4);
        o[0] = __floats2half2_rn(v.x, v.y);
        o[1] = __floats2half2_rn(v.z, v.w);
    } else if (i < 4L * NW) {
        long ii = i - 3L * NW;
        float4 v = ((const float4*)wo)[ii];
        __half2* o = (__half2*)(woh + ii * 4);
        o[0] = __floats2half2_rn(v.x, v.y);
        o[1] = __floats2half2_rn(v.z, v.w);
    } else if (i < 4L * NW + NF) {
        long ii = i - 4L * NW;
        float4 v = ((const float4*)w1)[ii];
        __half2* o = (__half2*)(w1h + ii * 4);
        o[0] = __floats2half2_rn(v.x, v.y);
        o[1] = __floats2half2_rn(v.z, v.w);
    } else if (i < 4L * NW + 2L * NF) {
        long ii = i - 4L * NW - NF;
        float4 v = ((const float4*)w2)[ii];
        __half2* o = (__half2*)(w2h + ii * 4);
        o[0] = __floats2half2_rn(v.x, v.y);
        o[1] = __floats2half2_rn(v.z, v.w);
    } else {
        long ii = i - 4L * NW - 2L * NF;
        if (ii < 768) {
            int j = (int)ii * 4;
            const float* src = (j < DD) ? bq : (j < 2 * DD) ? bk : bv;
            int jj = j & (DD - 1);
            *(float4*)(bqkv + j) = *(const float4*)(src + jj);
        }
    }
}
#define PACK_BLOCKS ((4L * NW + 2L * NF + 768 + 255) / 256)

// ---------------- LayerNorm (Bessel var, eps on std) -> fp16 out ------------
__global__ void __launch_bounds__(256) ln_kernel(
    const float* __restrict__ x, const float* __restrict__ gw,
    const float* __restrict__ bw, __half* __restrict__ y)
{
    int row = blockIdx.x;
    int t = threadIdx.x;
    const float4* xr = (const float4*)(x + (size_t)row * DD);
    float4 v = xr[t];
    float s  = v.x + v.y + v.z + v.w;
    float ss = v.x * v.x + v.y * v.y + v.z * v.z + v.w * v.w;

    __shared__ float rs[8], rss[8];
    #pragma unroll
    for (int o = 16; o; o >>= 1) {
        s  += __shfl_xor_sync(0xffffffffu, s,  o);
        ss += __shfl_xor_sync(0xffffffffu, ss, o);
    }
    if ((t & 31) == 0) { rs[t >> 5] = s; rss[t >> 5] = ss; }
    __syncthreads();
    __shared__ float mean_s, rd_s;
    if (t == 0) {
        float S = 0.f, SQ = 0.f;
        #pragma unroll
        for (int i = 0; i < 8; i++) { S += rs[i]; SQ += rss[i]; }
        float mean = S * (1.0f / DD);
        float var  = (SQ - S * S * (1.0f / DD)) * (1.0f / (DD - 1));
        var = fmaxf(var, 0.f);
        mean_s = mean;
        rd_s = 1.0f / (sqrtf(var) + 1e-6f);
    }
    __syncthreads();
    float mean = mean_s, rd = rd_s;
    float4 g4 = ((const float4*)gw)[t];
    float4 b4 = ((const float4*)bw)[t];
    __half2* o = (__half2*)(y + (size_t)row * DD + t * 4);
    o[0] = __floats2half2_rn(g4.x * (v.x - mean) * rd + b4.x,
                             g4.y * (v.y - mean) * rd + b4.y);
    o[1] = __floats2half2_rn(g4.z * (v.z - mean) * rd + b4.z,
                             g4.w * (v.w - mean) * rd + b4.w);
}

// ---------------- fp16 mma GEMM, templated N-tile ----------------------------
// BN=256: warp tile 64x64, 1 CTA/SM. BN=128: warp tile 64x32, 2 CTA/SM.
#define TKH 32
#define ASTRH 40
#define A_TILE_H (128 * ASTRH)
#define NSTG 4

template <int BN> struct GemmCfg {
    static const int BSTR = BN + 8;
    static const int B_TILE = TKH * BSTR;
    static const int STAGE = A_TILE_H + B_TILE;
    static const int SMEM = NSTG * STAGE * 2;
    static const int NT = BN / 32;        // n-tiles of 8 per warp
    static const int PP = BN / 64;        // ldm_x4t per ks per warp
    static const int BCH = BN / 8;        // cp16 chunks per B row
    static const int BITER = 32 * BCH / 256;
    static const int OCC = (BN == 128) ? 2 : 1;
};

// EPI: 1 = bias+gelu -> fp16 out, 2 = bias+residual -> fp32 out,
//      3 = bias -> fp16 out
template <int EPI, int BN>
__global__ void __launch_bounds__(256, GemmCfg<BN>::OCC) gemm_f16(
    const __half* __restrict__ A, const __half* __restrict__ W,
    const float* __restrict__ bias, const float* __restrict__ R,
    void* __restrict__ Cv, int M, int K, int N)
{
    typedef GemmCfg<BN> C;
    extern __shared__ __half smh[];
    uint32_t sbase = smem_u32(smh);
    int t = threadIdx.x;
    int m0 = blockIdx.y * 128, n0 = blockIdx.x * BN;
    int nkt = K >> 5;

    auto load_tile = [&](int stg, int kt) {
        __half* As = smh + stg * C::STAGE;
        __half* Bs = As + A_TILE_H;
        int k0 = kt * TKH;
        #pragma unroll
        for (int i = 0; i < 2; i++) {
            int id = t + i * 256;
            int row = id >> 2, c8 = (id & 3) << 3;
            cp16(As + row * ASTRH + c8, A + (size_t)(m0 + row) * K + k0 + c8);
        }
        #pragma unroll
        for (int i = 0; i < C::BITER; i++) {
            int id = t + i * 256;
            int row = id / C::BCH, c8 = (id % C::BCH) << 3;
            cp16(Bs + row * C::BSTR + c8, W + (size_t)(k0 + row) * N + n0 + c8);
        }
    };

    float acc[4][C::NT][4];
    #pragma unroll
    for (int mt = 0; mt < 4; mt++)
        #pragma unroll
        for (int nt = 0; nt < C::NT; nt++)
            #pragma unroll
            for (int i = 0; i < 4; i++) acc[mt][nt][i] = 0.f;

    int lane = t & 31, wid = t >> 5;
    int warpM = wid >> 2, warpN = wid & 3;
    int g = lane >> 2, c = lane & 3;
    int arow_l = lane & 15;
    int acol_l = (lane >> 4) << 3;
    int mat = lane >> 3, lr = lane & 7;
    int bko = ((mat & 1) << 3) + lr;
    int bno = (mat >> 1) << 3;

    #pragma unroll
    for (int s = 0; s < NSTG - 1; s++) { load_tile(s, s); cp_commit(); }

    for (int kt = 0; kt < nkt; kt++) {
        cp_wait<NSTG - 2>();
        __syncthreads();

        int nx = kt + NSTG - 1;
        if (nx < nkt) load_tile(nx & (NSTG - 1), nx);
        cp_commit();

        uint32_t As_u = sbase + (uint32_t)((kt & (NSTG - 1)) * C::STAGE) * 2;
        uint32_t Bs_u = As_u + A_TILE_H * 2;

        #pragma unroll
        for (int ks = 0; ks < 2; ks++) {
            uint32_t af[4][4];
            #pragma unroll
            for (int mt = 0; mt < 4; mt++)
                ldm_x4(af[mt], As_u +
                    ((uint32_t)((warpM * 64 + mt * 16 + arow_l) * ASTRH
                                + ks * 16 + acol_l) << 1));
            uint32_t b4[C::PP][4];
            #pragma unroll
            for (int p = 0; p < C::PP; p++) {
                int bk = ks * 16 + bko;
                int bn = warpN * (BN / 4) + p * 16 + bno;
                ldm_x4t(b4[p], Bs_u + ((uint32_t)(bk * C::BSTR + bn) << 1));
            }
            #pragma unroll
            for (int mt = 0; mt < 4; mt++)
                #pragma unroll
                for (int nt = 0; nt < C::NT; nt++)
                    mma16(acc[mt][nt], af[mt], &b4[nt >> 1][(nt & 1) << 1]);
        }
    }

    int rbase = m0 + warpM * 64 + g;
    int cbase = n0 + warpN * (BN / 4) + 2 * c;

    #pragma unroll
    for (int nt = 0; nt < C::NT; nt++) {
        int col = cbase + nt * 8;
        float2 b2 = *(const float2*)(bias + col);
        #pragma unroll
        for (int mt = 0; mt < 4; mt++) {
            int r0 = rbase + mt * 16;
            float v0x = acc[mt][nt][0] + b2.x;
            float v0y = acc[mt][nt][1] + b2.y;
            float v1x = acc[mt][nt][2] + b2.x;
            float v1y = acc[mt][nt][3] + b2.y;
            if (EPI == 2) {
                float* Co = (float*)Cv;
                float2 r0v = *(const float2*)(R + (size_t)r0 * N + col);
                float2 r1v = *(const float2*)(R + (size_t)(r0 + 8) * N + col);
                *(float2*)(Co + (size_t)r0 * N + col) =
                    make_float2(v0x + r0v.x, v0y + r0v.y);
                *(float2*)(Co + (size_t)(r0 + 8) * N + col) =
                    make_float2(v1x + r1v.x, v1y + r1v.y);
            } else {
                if (EPI == 1) {
                    v0x = gelu_tanh_f(v0x); v0y = gelu_tanh_f(v0y);
                    v1x = gelu_tanh_f(v1x); v1y = gelu_tanh_f(v1y);
                }
                __half* Co = (__half*)Cv;
                *(__half2*)(Co + (size_t)r0 * N + col) = __floats2half2_rn(v0x, v0y);
                *(__half2*)(Co + (size_t)(r0 + 8) * N + col) = __floats2half2_rn(v1x, v1y);
            }
        }
    }
}

// ---------------- fp16 tensor-core flash attention ---------------------------
// 3-stage KV pipeline, single sync per iteration, log2-domain softmax.
#define FQSTR 72
#define FQ_H (128 * FQSTR)
#define FKV_H (64 * FQSTR)
#define KOFF FQ_H
#define VOFF (FQ_H + 3 * FKV_H)
#define MOFF_BYTES ((FQ_H + 6 * FKV_H) * 2)
#define FLASH_SMEM (MOFF_BYTES + 3 * 64 * 4 + 16)
#define QSCALE 0.1803368801111204f   /* 0.125 * log2(e) */
#define MBIAS  (-1.44269504e9f)      /* -1e9 * log2(e)  */

__global__ void __launch_bounds__(256, 2) flash_f16(
    const __half* __restrict__ Q, const __half* __restrict__ Kg,
    const __half* __restrict__ Vg, int ldq, const int* __restrict__ mask,
    __half* __restrict__ O)
{
    extern __shared__ __half smh[];
    uint32_t sbase = smem_u32(smh);
    int* mksm = (int*)((char*)smh + MOFF_BYTES);
    int t = threadIdx.x;
    int lane = t & 31, wid = t >> 5;
    int g = lane >> 2, c = lane & 3;
    int q0 = blockIdx.x * 128;
    int h = blockIdx.y, b = blockIdx.z;
    size_t baseQ = ((size_t)(b * SS + q0)) * ldq + h * DHD;

    auto load_kv = [&](int kt, int s) {
        size_t baseK = ((size_t)(b * SS + kt * 64)) * ldq + h * DHD;
        __half* Kb = smh + KOFF + s * FKV_H;
        __half* Vb = smh + VOFF + s * FKV_H;
        #pragma unroll
        for (int i = 0; i < 2; i++) {
            int id = t + i * 256;
            int row = id >> 3, c8 = (id & 7) << 3;
            cp16(Kb + row * FQSTR + c8, Kg + baseK + (size_t)row * ldq + c8);
            cp16(Vb + row * FQSTR + c8, Vg + baseK + (size_t)row * ldq + c8);
        }
        if (t < 16) cp16(mksm + s * 64 + t * 4, mask + b * SS + kt * 64 + t * 4);
    };

    load_kv(0, 0);
    #pragma unroll
    for (int i = 0; i < 4; i++) {
        int id = t + i * 256;
        int row = id >> 3, c8 = (id & 7) << 3;
        cp16(smh + row * FQSTR + c8, Q + baseQ + (size_t)row * ldq + c8);
    }
    cp_commit();
    load_kv(1, 1);
    cp_commit();

    cp_wait<1>();
    __syncthreads();

    int arow_l = lane & 15;
    int acol_l = (lane >> 4) << 3;
    int mat = lane >> 3, lr = lane & 7;
    uint32_t qf[4][4];
    int qb = wid * 16;
    {
        __half2 qs = __float2half2_rn(QSCALE);
        #pragma unroll
        for (int ks = 0; ks < 4; ks++) {
            ldm_x4(qf[ks], sbase +
                ((uint32_t)((qb + arow_l) * FQSTR + ks * 16 + acol_l) << 1));
            #pragma unroll
            for (int i = 0; i < 4; i++) {
                __half2 hv = *(__half2*)&qf[ks][i];
                hv = __hmul2(hv, qs);
                qf[ks][i] = *(uint32_t*)&hv;
            }
        }
    }

    float m0 = -1e30f, m1 = -1e30f, l0 = 0.f, l1 = 0.f;
    float acc[8][4];
    #pragma unroll
    for (int nt = 0; nt < 8; nt++)
        #pragma unroll
        for (int i = 0; i < 4; i++) acc[nt][i] = 0.f;

    for (int kt = 0; kt < SS / 64; kt++) {
        cp_wait<1>();
        __syncthreads();

        int nx = kt + 2;
        if (nx < SS / 64) load_kv(nx, nx % 3);
        cp_commit();

        int st = kt % 3;
        uint32_t Ku = sbase + (uint32_t)((KOFF + st * FKV_H) * 2);
        uint32_t Vu = sbase + (uint32_t)((VOFF + st * FKV_H) * 2);
        const int* mk = mksm + st * 64;

        float sf[8][4];
        #pragma unroll
        for (int nt = 0; nt < 8; nt++)
            #pragma unroll
            for (int i = 0; i < 4; i++) sf[nt][i] = 0.f;

        #pragma unroll
        for (int ks = 0; ks < 4; ks++) {
            int kk = ks * 16 + ((mat & 1) << 3);
            #pragma unroll
            for (int p = 0; p < 4; p++) {
                int kn = p * 16 + ((mat >> 1) << 3) + lr;
                uint32_t kb[4];
                ldm_x4(kb, Ku + ((uint32_t)(kn * FQSTR + kk) << 1));
                mma16(sf[2 * p],     qf[ks], kb);
                mma16(sf[2 * p + 1], qf[ks], kb + 2);
            }
        }

        // softmax in log2 domain (scale pre-folded into Q)
        float mx0 = -1e30f, mx1 = -1e30f;
        #pragma unroll
        for (int nt = 0; nt < 8; nt++) {
            float bia0 = mk[nt * 8 + 2 * c]     ? 0.f : MBIAS;
            float bia1 = mk[nt * 8 + 2 * c + 1] ? 0.f : MBIAS;
            sf[nt][0] += bia0; sf[nt][1] += bia1;
            sf[nt][2] += bia0; sf[nt][3] += bia1;
            mx0 = fmaxf(mx0, fmaxf(sf[nt][0], sf[nt][1]));
            mx1 = fmaxf(mx1, fmaxf(sf[nt][2], sf[nt][3]));
        }
        mx0 = fmaxf(mx0, __shfl_xor_sync(0xffffffffu, mx0, 1));
        mx0 = fmaxf(mx0, __shfl_xor_sync(0xffffffffu, mx0, 2));
        mx1 = fmaxf(mx1, __shfl_xor_sync(0xffffffffu, mx1, 1));
        mx1 = fmaxf(mx1, __shfl_xor_sync(0xffffffffu, mx1, 2));

        float mn0 = fmaxf(m0, mx0), mn1 = fmaxf(m1, mx1);
        float al0 = ex2f(m0 - mn0), al1 = ex2f(m1 - mn1);
        m0 = mn0; m1 = mn1;

        float ps0 = 0.f, ps1 = 0.f;
        #pragma unroll
        for (int nt = 0; nt < 8; nt++) {
            sf[nt][0] = ex2f(sf[nt][0] - mn0);
            sf[nt][1] = ex2f(sf[nt][1] - mn0);
            sf[nt][2] = ex2f(sf[nt][2] - mn1);
            sf[nt][3] = ex2f(sf[nt][3] - mn1);
            ps0 += sf[nt][0] + sf[nt][1];
            ps1 += sf[nt][2] + sf[nt][3];
        }
        ps0 += __shfl_xor_sync(0xffffffffu, ps0, 1);
        ps0 += __shfl_xor_sync(0xffffffffu, ps0, 2);
        ps1 += __shfl_xor_sync(0xffffffffu, ps1, 1);
        ps1 += __shfl_xor_sync(0xffffffffu, ps1, 2);
        l0 = l0 * al0 + ps0;
        l1 = l1 * al1 + ps1;

        #pragma unroll
        for (int nt = 0; nt < 8; nt++) {
            acc[nt][0] *= al0; acc[nt][1] *= al0;
            acc[nt][2] *= al1; acc[nt][3] *= al1;
        }

        #pragma unroll
        for (int ks = 0; ks < 4; ks++) {
            uint32_t af[4];
            af[0] = packh2(sf[2 * ks][0],     sf[2 * ks][1]);
            af[1] = packh2(sf[2 * ks][2],     sf[2 * ks][3]);
            af[2] = packh2(sf[2 * ks + 1][0], sf[2 * ks + 1][1]);
            af[3] = packh2(sf[2 * ks + 1][2], sf[2 * ks + 1][3]);
            int vk = ks * 16 + ((mat & 1) << 3) + lr;
            #pragma unroll
            for (int p = 0; p < 4; p++) {
                int vn = p * 16 + ((mat >> 1) << 3);
                uint32_t vb[4];
                ldm_x4t(vb, Vu + ((uint32_t)(vk * FQSTR + vn) << 1));
                mma16(acc[2 * p],     af, vb);
                mma16(acc[2 * p + 1], af, vb + 2);
            }
        }
    }

    float inv0 = 1.f / l0, inv1 = 1.f / l1;
    size_t r0 = ((size_t)(b * SS + q0 + qb + g)) * DD + h * DHD;
    size_t r1 = r0 + 8 * DD;
    #pragma unroll
    for (int nt = 0; nt < 8; nt++) {
        int col = nt * 8 + 2 * c;
        *(__half2*)(O + r0 + col) =
            __floats2half2_rn(acc[nt][0] * inv0, acc[nt][1] * inv0);
        *(__half2*)(O + r1 + col) =
            __floats2half2_rn(acc[nt][2] * inv1, acc[nt][3] * inv1);
    }
}

// ---------------- launch ---------------------------------------------------
extern "C" void kernel_launch(void* const* d_in, const int* in_sizes, int n_in,
                              void* d_out, int out_size)
{
    const float* hidden = (const float*)d_in[0];
    const int*   mask   = (const int*)d_in[1];
    const float* wq = (const float*)d_in[2];
    const float* bq = (const float*)d_in[3];
    const float* wk = (const float*)d_in[4];
    const float* bk = (const float*)d_in[5];
    const float* wv = (const float*)d_in[6];
    const float* bv = (const float*)d_in[7];
    const float* wo = (const float*)d_in[8];
    const float* bo = (const float*)d_in[9];
    const float* w1 = (const float*)d_in[10];
    const float* b1 = (const float*)d_in[11];
    const float* w2 = (const float*)d_in[12];
    const float* b2 = (const float*)d_in[13];
    const float* ln1_g = (const float*)d_in[14];
    const float* ln1_b = (const float*)d_in[15];
    const float* ln2_g = (const float*)d_in[16];
    const float* ln2_b = (const float*)d_in[17];
    float* out = (float*)d_out;

    __half *ln, *qkv, *attn, *f1, *wqkvh, *woh, *w1h, *w2h;
    float *h1, *bqkv;
    cudaGetSymbolAddress((void**)&ln,    g_ln);
    cudaGetSymbolAddress((void**)&qkv,   g_qkv);
    cudaGetSymbolAddress((void**)&attn,  g_attn);
    cudaGetSymbolAddress((void**)&h1,    g_h1);
    cudaGetSymbolAddress((void**)&f1,    g_f1);
    cudaGetSymbolAddress((void**)&wqkvh, g_wqkv);
    cudaGetSymbolAddress((void**)&bqkv,  g_bqkv);
    cudaGetSymbolAddress((void**)&woh,   g_wo);
    cudaGetSymbolAddress((void**)&w1h,   g_w1);
    cudaGetSymbolAddress((void**)&w2h,   g_w2);

    cudaFuncSetAttribute(flash_f16,
                         cudaFuncAttributeMaxDynamicSharedMemorySize, FLASH_SMEM);
    cudaFuncSetAttribute(gemm_f16<3, 256>,
                         cudaFuncAttributeMaxDynamicSharedMemorySize, GemmCfg<256>::SMEM);
    cudaFuncSetAttribute(gemm_f16<1, 256>,
                         cudaFuncAttributeMaxDynamicSharedMemorySize, GemmCfg<256>::SMEM);
    cudaFuncSetAttribute(gemm_f16<2, 128>,
                         cudaFuncAttributeMaxDynamicSharedMemorySize, GemmCfg<128>::SMEM);

    // one fused pack launch
    pack_all<<<(unsigned)PACK_BLOCKS, 256>>>(wq, wk, wv, wo, w1, w2, bq, bk, bv,
                                             wqkvh, woh, w1h, w2h, bqkv);

    // 1) LN1
    ln_kernel<<<NROWS, 256>>>(hidden, ln1_g, ln1_b, ln);

    // 2) fused QKV projection -> fp16  (128x256 tile)
    dim3 gQKV(NQKV / 256, NROWS / 128);
    gemm_f16<3, 256><<<gQKV, 256, GemmCfg<256>::SMEM>>>(ln, wqkvh, bqkv, nullptr,
                                                        qkv, NROWS, DD, NQKV);

    // 3) attention
    flash_f16<<<dim3(SS / 128, HH, BB), 256, FLASH_SMEM>>>(
        qkv, qkv + DD, qkv + 2 * DD, NQKV, mask, attn);

    // 4) output projection + residual -> fp32  (128x128 tile, 2 CTA/SM)
    dim3 gD(DD / 128, NROWS / 128);
    gemm_f16<2, 128><<<gD, 256, GemmCfg<128>::SMEM>>>(attn, woh, bo, hidden, h1,
                                                      NROWS, DD, DD);

    // 5) LN2
    ln_kernel<<<NROWS, 256>>>(h1, ln2_g, ln2_b, ln);

    // 6) FFN
    dim3 gF(DFF / 256, NROWS / 128);
    gemm_f16<1, 256><<<gF, 256, GemmCfg<256>::SMEM>>>(ln, w1h, b1, nullptr, f1,
                                                      NROWS, DD, DFF);
    gemm_f16<2, 128><<<gD, 256, GemmCfg<128>::SMEM>>>(f1, w2h, b2, h1, out,
                                                      NROWS, DFF, DD);
}

// round 9
// speedup vs baseline: 1.0878x; 1.0878x over previous
#include <cuda_runtime.h>
#include <cuda_fp16.h>
#include <math.h>
#include <stdint.h>

#define BB 2
#define SS 2048
#define DD 1024
#define HH 16
#define DHD 64
#define DFF 4096
#define NROWS (BB * SS)
#define NQKV 3072

// ---------------- scratch (device globals; no allocation) ----------------
__device__ __half g_ln[NROWS * DD];
__device__ __half g_qkv[NROWS * NQKV];
__device__ __half g_attn[NROWS * DD];
__device__ float  g_h1[NROWS * DD];
__device__ __half g_f1[NROWS * DFF];
__device__ __half g_wqkv[DD * NQKV];
__device__ float  g_bqkv[NQKV];
__device__ __half g_wo[DD * DD];
__device__ __half g_w1[DD * DFF];
__device__ __half g_w2[DFF * DD];

// ---------------- helpers --------------------------------------------------
__device__ __forceinline__ uint32_t smem_u32(const void* p) {
    uint32_t a;
    asm("{ .reg .u64 t; cvta.to.shared.u64 t, %1; cvt.u32.u64 %0, t; }" : "=r"(a) : "l"(p));
    return a;
}
__device__ __forceinline__ void cp16(void* dst_smem, const void* src) {
    uint32_t d;
    asm("{ .reg .u64 t; cvta.to.shared.u64 t, %1; cvt.u32.u64 %0, t; }"
        : "=r"(d) : "l"(dst_smem));
    asm volatile("cp.async.cg.shared.global [%0], [%1], 16;" :: "r"(d), "l"(src));
}
__device__ __forceinline__ void cp_commit() {
    asm volatile("cp.async.commit_group;");
}
template <int N>
__device__ __forceinline__ void cp_wait() {
    asm volatile("cp.async.wait_group %0;" :: "n"(N));
}
__device__ __forceinline__ void ldm_x4(uint32_t r[4], uint32_t addr) {
    asm volatile("ldmatrix.sync.aligned.m8n8.x4.shared.b16 {%0,%1,%2,%3}, [%4];"
        : "=r"(r[0]), "=r"(r[1]), "=r"(r[2]), "=r"(r[3]) : "r"(addr));
}
__device__ __forceinline__ void ldm_x4t(uint32_t r[4], uint32_t addr) {
    asm volatile("ldmatrix.sync.aligned.m8n8.x4.trans.shared.b16 {%0,%1,%2,%3}, [%4];"
        : "=r"(r[0]), "=r"(r[1]), "=r"(r[2]), "=r"(r[3]) : "r"(addr));
}
__device__ __forceinline__ void mma16(float c[4], const uint32_t a[4], const uint32_t b[2]) {
    asm volatile(
        "mma.sync.aligned.m16n8k16.row.col.f32.f16.f16.f32 "
        "{%0,%1,%2,%3}, {%4,%5,%6,%7}, {%8,%9}, {%0,%1,%2,%3};"
        : "+f"(c[0]), "+f"(c[1]), "+f"(c[2]), "+f"(c[3])
        : "r"(a[0]), "r"(a[1]), "r"(a[2]), "r"(a[3]), "r"(b[0]), "r"(b[1]));
}
__device__ __forceinline__ uint32_t packh2(float lo, float hi) {
    __half2 h = __floats2half2_rn(lo, hi);
    return *(uint32_t*)&h;
}
__device__ __forceinline__ float ex2f(float x) {
    float r;
    asm("ex2.approx.f32 %0, %1;" : "=f"(r) : "f"(x));
    return r;
}
__device__ __forceinline__ float gelu_tanh_f(float h) {
    const float c = 0.7978845608028654f;
    float u = c * (h + 0.044715f * h * h * h);
    return 0.5f * h * (1.0f + tanhf(u));
}

// ---------------- ONE fused pack kernel (all weights + biases) -------------
#define NW (DD * DD / 4)
#define NF (DD * DFF / 4)
__global__ void __launch_bounds__(256) pack_all(
    const float* __restrict__ wq, const float* __restrict__ wk,
    const float* __restrict__ wv, const float* __restrict__ wo,
    const float* __restrict__ w1, const float* __restrict__ w2,
    const float* __restrict__ bq, const float* __restrict__ bk,
    const float* __restrict__ bv,
    __half* __restrict__ wqkv, __half* __restrict__ woh,
    __half* __restrict__ w1h, __half* __restrict__ w2h,
    float* __restrict__ bqkv)
{
    long i = (long)blockIdx.x * 256 + threadIdx.x;
    if (i < 3L * NW) {
        const float* src = (i < NW) ? wq : (i < 2L * NW) ? wk : wv;
        int coff = (i < NW) ? 0 : (i < 2L * NW) ? DD : 2 * DD;
        long ii = i % NW;
        int row = (int)(ii >> 8), c4 = ((int)ii & 255) << 2;
        float4 v = ((const float4*)src)[ii];
        __half2* o = (__half2*)(wqkv + (size_t)row * NQKV + coff + c4);
        o[0] = __floats2half2_rn(v.x, v.y);
        o[1] = __floats2half2_rn(v.z, v.w);
    } else if (i < 4L * NW) {
        long ii = i - 3L * NW;
        float4 v = ((const float4*)wo)[ii];
        __half2* o = (__half2*)(woh + ii * 4);
        o[0] = __floats2half2_rn(v.x, v.y);
        o[1] = __floats2half2_rn(v.z, v.w);
    } else if (i < 4L * NW + NF) {
        long ii = i - 4L * NW;
        float4 v = ((const float4*)w1)[ii];
        __half2* o = (__half2*)(w1h + ii * 4);
        o[0] = __floats2half2_rn(v.x, v.y);
        o[1] = __floats2half2_rn(v.z, v.w);
    } else if (i < 4L * NW + 2L * NF) {
        long ii = i - 4L * NW - NF;
        float4 v = ((const float4*)w2)[ii];
        __half2* o = (__half2*)(w2h + ii * 4);
        o[0] = __floats2half2_rn(v.x, v.y);
        o[1] = __floats2half2_rn(v.z, v.w);
    } else {
        long ii = i - 4L * NW - 2L * NF;
        if (ii < 768) {
            int j = (int)ii * 4;
            const float* src = (j < DD) ? bq : (j < 2 * DD) ? bk : bv;
            int jj = j & (DD - 1);
            *(float4*)(bqkv + j) = *(const float4*)(src + jj);
        }
    }
}
#define PACK_BLOCKS ((4L * NW + 2L * NF + 768 + 255) / 256)

// ---------------- LayerNorm: one warp per row, shfl-only -------------------
__global__ void __launch_bounds__(256) ln_kernel(
    const float* __restrict__ x, const float* __restrict__ gw,
    const float* __restrict__ bw, __half* __restrict__ y)
{
    int warp = threadIdx.x >> 5, lane = threadIdx.x & 31;
    int row = blockIdx.x * 8 + warp;
    const float4* xr = (const float4*)(x + (size_t)row * DD);

    float4 v[8];
    float s = 0.f, ss = 0.f;
    #pragma unroll
    for (int i = 0; i < 8; i++) {
        v[i] = xr[lane + i * 32];
        s  += v[i].x + v[i].y + v[i].z + v[i].w;
        ss += v[i].x * v[i].x + v[i].y * v[i].y + v[i].z * v[i].z + v[i].w * v[i].w;
    }
    #pragma unroll
    for (int o = 16; o; o >>= 1) {
        s  += __shfl_xor_sync(0xffffffffu, s,  o);
        ss += __shfl_xor_sync(0xffffffffu, ss, o);
    }
    float mean = s * (1.0f / DD);
    float var  = (ss - s * s * (1.0f / DD)) * (1.0f / (DD - 1));
    var = fmaxf(var, 0.f);
    float rd = 1.0f / (sqrtf(var) + 1e-6f);

    __half2* yo = (__half2*)(y + (size_t)row * DD);
    #pragma unroll
    for (int i = 0; i < 8; i++) {
        float4 g4 = ((const float4*)gw)[lane + i * 32];
        float4 b4 = ((const float4*)bw)[lane + i * 32];
        yo[2 * (lane + i * 32)] =
            __floats2half2_rn(g4.x * (v[i].x - mean) * rd + b4.x,
                              g4.y * (v[i].y - mean) * rd + b4.y);
        yo[2 * (lane + i * 32) + 1] =
            __floats2half2_rn(g4.z * (v[i].z - mean) * rd + b4.z,
                              g4.w * (v[i].w - mean) * rd + b4.w);
    }
}

// ---------------- fp16 mma GEMM (128x128x32, 8 warps, 2 CTA/SM) -------------
#define TKH 32
#define ASTRH 40
#define BSTRH 136
#define A_TILE_H (128 * ASTRH)
#define B_TILE_H (TKH * BSTRH)
#define STAGE_H (A_TILE_H + B_TILE_H)
#define NSTG 4
#define GEMM_SMEM (NSTG * STAGE_H * 2)

// EPI: 1 = bias+gelu -> fp16 out, 2 = bias+residual -> fp32 out,
//      3 = bias -> fp16 out
template <int EPI>
__global__ void __launch_bounds__(256, 2) gemm_f16(
    const __half* __restrict__ A, const __half* __restrict__ W,
    const float* __restrict__ bias, const float* __restrict__ R,
    void* __restrict__ Cv, int M, int K, int N)
{
    extern __shared__ __half smh[];
    uint32_t sbase = smem_u32(smh);
    int t = threadIdx.x;
    int m0 = blockIdx.y * 128, n0 = blockIdx.x * 128;
    int nkt = K >> 5;

    auto load_tile = [&](int stg, int kt) {
        __half* As = smh + stg * STAGE_H;
        __half* Bs = As + A_TILE_H;
        int k0 = kt * TKH;
        #pragma unroll
        for (int i = 0; i < 2; i++) {
            int id = t + i * 256;
            int row = id >> 2, c8 = (id & 3) << 3;
            cp16(As + row * ASTRH + c8, A + (size_t)(m0 + row) * K + k0 + c8);
        }
        #pragma unroll
        for (int i = 0; i < 2; i++) {
            int id = t + i * 256;
            int row = id >> 4, c8 = (id & 15) << 3;
            cp16(Bs + row * BSTRH + c8, W + (size_t)(k0 + row) * N + n0 + c8);
        }
    };

    float acc[4][4][4];
    #pragma unroll
    for (int mt = 0; mt < 4; mt++)
        #pragma unroll
        for (int nt = 0; nt < 4; nt++)
            #pragma unroll
            for (int i = 0; i < 4; i++) acc[mt][nt][i] = 0.f;

    int lane = t & 31, wid = t >> 5;
    int warpM = wid >> 2, warpN = wid & 3;
    int g = lane >> 2, c = lane & 3;
    int arow_l = lane & 15;
    int acol_l = (lane >> 4) << 3;
    int mat = lane >> 3, lr = lane & 7;
    int bko = ((mat & 1) << 3) + lr;
    int bno = (mat >> 1) << 3;

    #pragma unroll
    for (int s = 0; s < NSTG - 1; s++) { load_tile(s, s); cp_commit(); }

    for (int kt = 0; kt < nkt; kt++) {
        cp_wait<NSTG - 2>();
        __syncthreads();

        int nx = kt + NSTG - 1;
        if (nx < nkt) load_tile(nx & (NSTG - 1), nx);
        cp_commit();

        uint32_t As_u = sbase + (uint32_t)((kt & (NSTG - 1)) * STAGE_H) * 2;
        uint32_t Bs_u = As_u + A_TILE_H * 2;

        #pragma unroll
        for (int ks = 0; ks < 2; ks++) {
            uint32_t af[4][4];
            #pragma unroll
            for (int mt = 0; mt < 4; mt++)
                ldm_x4(af[mt], As_u +
                    ((uint32_t)((warpM * 64 + mt * 16 + arow_l) * ASTRH
                                + ks * 16 + acol_l) << 1));
            uint32_t b4[2][4];
            #pragma unroll
            for (int p = 0; p < 2; p++) {
                int bk = ks * 16 + bko;
                int bn = warpN * 32 + p * 16 + bno;
                ldm_x4t(b4[p], Bs_u + ((uint32_t)(bk * BSTRH + bn) << 1));
            }
            #pragma unroll
            for (int mt = 0; mt < 4; mt++)
                #pragma unroll
                for (int nt = 0; nt < 4; nt++)
                    mma16(acc[mt][nt], af[mt], &b4[nt >> 1][(nt & 1) << 1]);
        }
    }

    int rbase = m0 + warpM * 64 + g;
    int cbase = n0 + warpN * 32 + 2 * c;

    #pragma unroll
    for (int nt = 0; nt < 4; nt++) {
        int col = cbase + nt * 8;
        float2 b2 = *(const float2*)(bias + col);
        #pragma unroll
        for (int mt = 0; mt < 4; mt++) {
            int r0 = rbase + mt * 16;
            float v0x = acc[mt][nt][0] + b2.x;
            float v0y = acc[mt][nt][1] + b2.y;
            float v1x = acc[mt][nt][2] + b2.x;
            float v1y = acc[mt][nt][3] + b2.y;
            if (EPI == 2) {
                float* C = (float*)Cv;
                float2 r0v = *(const float2*)(R + (size_t)r0 * N + col);
                float2 r1v = *(const float2*)(R + (size_t)(r0 + 8) * N + col);
                *(float2*)(C + (size_t)r0 * N + col) =
                    make_float2(v0x + r0v.x, v0y + r0v.y);
                *(float2*)(C + (size_t)(r0 + 8) * N + col) =
                    make_float2(v1x + r1v.x, v1y + r1v.y);
            } else {
                if (EPI == 1) {
                    v0x = gelu_tanh_f(v0x); v0y = gelu_tanh_f(v0y);
                    v1x = gelu_tanh_f(v1x); v1y = gelu_tanh_f(v1y);
                }
                __half* C = (__half*)Cv;
                *(__half2*)(C + (size_t)r0 * N + col) = __floats2half2_rn(v0x, v0y);
                *(__half2*)(C + (size_t)(r0 + 8) * N + col) = __floats2half2_rn(v1x, v1y);
            }
        }
    }
}

// ---------------- fp16 tensor-core flash attention ---------------------------
// 4-stage KV pipeline, stage loop unrolled (compile-time stage offsets).
#define FQSTR 72
#define FQ_H (128 * FQSTR)
#define FKV_H (64 * FQSTR)
#define KOFF FQ_H
#define VOFF (FQ_H + 4 * FKV_H)
#define MOFF_BYTES ((FQ_H + 8 * FKV_H) * 2)
#define FLASH_SMEM (MOFF_BYTES + 4 * 64 * 4 + 16)
#define QSCALE 0.1803368801111204f   /* 0.125 * log2(e) */
#define MBIAS  (-1.44269504e9f)      /* -1e9 * log2(e)  */

__global__ void __launch_bounds__(256, 2) flash_f16(
    const __half* __restrict__ Q, const __half* __restrict__ Kg,
    const __half* __restrict__ Vg, int ldq, const int* __restrict__ mask,
    __half* __restrict__ O)
{
    extern __shared__ __half smh[];
    uint32_t sbase = smem_u32(smh);
    int* mksm = (int*)((char*)smh + MOFF_BYTES);
    int t = threadIdx.x;
    int lane = t & 31, wid = t >> 5;
    int g = lane >> 2, c = lane & 3;
    int q0 = blockIdx.x * 128;
    int h = blockIdx.y, b = blockIdx.z;
    size_t baseQ = ((size_t)(b * SS + q0)) * ldq + h * DHD;

    auto load_kv = [&](int kt, int s) {
        size_t baseK = ((size_t)(b * SS + kt * 64)) * ldq + h * DHD;
        __half* Kb = smh + KOFF + s * FKV_H;
        __half* Vb = smh + VOFF + s * FKV_H;
        #pragma unroll
        for (int i = 0; i < 2; i++) {
            int id = t + i * 256;
            int row = id >> 3, c8 = (id & 7) << 3;
            cp16(Kb + row * FQSTR + c8, Kg + baseK + (size_t)row * ldq + c8);
            cp16(Vb + row * FQSTR + c8, Vg + baseK + (size_t)row * ldq + c8);
        }
        if (t < 16) cp16(mksm + s * 64 + t * 4, mask + b * SS + kt * 64 + t * 4);
    };

    // prologue: kv0+Q, kv1, kv2 (3 groups in flight)
    load_kv(0, 0);
    #pragma unroll
    for (int i = 0; i < 4; i++) {
        int id = t + i * 256;
        int row = id >> 3, c8 = (id & 7) << 3;
        cp16(smh + row * FQSTR + c8, Q + baseQ + (size_t)row * ldq + c8);
    }
    cp_commit();
    load_kv(1, 1);
    cp_commit();
    load_kv(2, 2);
    cp_commit();

    cp_wait<2>();
    __syncthreads();

    int arow_l = lane & 15;
    int acol_l = (lane >> 4) << 3;
    int mat = lane >> 3, lr = lane & 7;
    uint32_t qf[4][4];
    int qb = wid * 16;
    {
        __half2 qs = __float2half2_rn(QSCALE);
        #pragma unroll
        for (int ks = 0; ks < 4; ks++) {
            ldm_x4(qf[ks], sbase +
                ((uint32_t)((qb + arow_l) * FQSTR + ks * 16 + acol_l) << 1));
            #pragma unroll
            for (int i = 0; i < 4; i++) {
                __half2 hv = *(__half2*)&qf[ks][i];
                hv = __hmul2(hv, qs);
                qf[ks][i] = *(uint32_t*)&hv;
            }
        }
    }

    float m0 = -1e30f, m1 = -1e30f, l0 = 0.f, l1 = 0.f;
    float acc[8][4];
    #pragma unroll
    for (int nt = 0; nt < 8; nt++)
        #pragma unroll
        for (int i = 0; i < 4; i++) acc[nt][i] = 0.f;

    // warp-invariant fragment offsets (compile-time per stage after unroll)
    uint32_t kfrag_base = sbase + ((uint32_t)(((mat >> 1) << 3) + lr) * FQSTR
                                   + ((mat & 1) << 3)) * 2 + KOFF * 2;
    uint32_t vfrag_base = sbase + ((uint32_t)((((mat & 1) << 3) + lr) * FQSTR)
                                   + (((mat >> 1) << 3))) * 2 + VOFF * 2;

    for (int kto = 0; kto < SS / 64; kto += 4) {
        #pragma unroll
        for (int st = 0; st < 4; st++) {
            int kt = kto + st;
            cp_wait<2>();
            __syncthreads();

            int nx = kt + 3;
            if (nx < SS / 64) load_kv(nx, nx & 3);
            cp_commit();

            const int* mk = mksm + st * 64;

            float sf[8][4];
            #pragma unroll
            for (int nt = 0; nt < 8; nt++)
                #pragma unroll
                for (int i = 0; i < 4; i++) sf[nt][i] = 0.f;

            #pragma unroll
            for (int ks = 0; ks < 4; ks++) {
                #pragma unroll
                for (int p = 0; p < 4; p++) {
                    uint32_t kb[4];
                    ldm_x4(kb, kfrag_base + (uint32_t)(st * FKV_H * 2)
                               + (uint32_t)((p * 16 * FQSTR + ks * 16) << 1));
                    mma16(sf[2 * p],     qf[ks], kb);
                    mma16(sf[2 * p + 1], qf[ks], kb + 2);
                }
            }

            float mx0 = -1e30f, mx1 = -1e30f;
            #pragma unroll
            for (int nt = 0; nt < 8; nt++) {
                float bia0 = mk[nt * 8 + 2 * c]     ? 0.f : MBIAS;
                float bia1 = mk[nt * 8 + 2 * c + 1] ? 0.f : MBIAS;
                sf[nt][0] += bia0; sf[nt][1] += bia1;
                sf[nt][2] += bia0; sf[nt][3] += bia1;
                mx0 = fmaxf(mx0, fmaxf(sf[nt][0], sf[nt][1]));
                mx1 = fmaxf(mx1, fmaxf(sf[nt][2], sf[nt][3]));
            }
            mx0 = fmaxf(mx0, __shfl_xor_sync(0xffffffffu, mx0, 1));
            mx0 = fmaxf(mx0, __shfl_xor_sync(0xffffffffu, mx0, 2));
            mx1 = fmaxf(mx1, __shfl_xor_sync(0xffffffffu, mx1, 1));
            mx1 = fmaxf(mx1, __shfl_xor_sync(0xffffffffu, mx1, 2));

            float mn0 = fmaxf(m0, mx0), mn1 = fmaxf(m1, mx1);
            float al0 = ex2f(m0 - mn0), al1 = ex2f(m1 - mn1);
            m0 = mn0; m1 = mn1;

            float ps0 = 0.f, ps1 = 0.f;
            #pragma unroll
            for (int nt = 0; nt < 8; nt++) {
                sf[nt][0] = ex2f(sf[nt][0] - mn0);
                sf[nt][1] = ex2f(sf[nt][1] - mn0);
                sf[nt][2] = ex2f(sf[nt][2] - mn1);
                sf[nt][3] = ex2f(sf[nt][3] - mn1);
                ps0 += sf[nt][0] + sf[nt][1];
                ps1 += sf[nt][2] + sf[nt][3];
            }
            ps0 += __shfl_xor_sync(0xffffffffu, ps0, 1);
            ps0 += __shfl_xor_sync(0xffffffffu, ps0, 2);
            ps1 += __shfl_xor_sync(0xffffffffu, ps1, 1);
            ps1 += __shfl_xor_sync(0xffffffffu, ps1, 2);
            l0 = l0 * al0 + ps0;
            l1 = l1 * al1 + ps1;

            #pragma unroll
            for (int nt = 0; nt < 8; nt++) {
                acc[nt][0] *= al0; acc[nt][1] *= al0;
                acc[nt][2] *= al1; acc[nt][3] *= al1;
            }

            #pragma unroll
            for (int ks = 0; ks < 4; ks++) {
                uint32_t af[4];
                af[0] = packh2(sf[2 * ks][0],     sf[2 * ks][1]);
                af[1] = packh2(sf[2 * ks][2],     sf[2 * ks][3]);
                af[2] = packh2(sf[2 * ks + 1][0], sf[2 * ks + 1][1]);
                af[3] = packh2(sf[2 * ks + 1][2], sf[2 * ks + 1][3]);
                #pragma unroll
                for (int p = 0; p < 4; p++) {
                    uint32_t vb[4];
                    ldm_x4t(vb, vfrag_base + (uint32_t)(st * FKV_H * 2)
                                + (uint32_t)((ks * 16 * FQSTR + p * 16) << 1));
                    mma16(acc[2 * p],     af, vb);
                    mma16(acc[2 * p + 1], af, vb + 2);
                }
            }
        }
    }

    float inv0 = 1.f / l0, inv1 = 1.f / l1;
    size_t r0 = ((size_t)(b * SS + q0 + qb + g)) * DD + h * DHD;
    size_t r1 = r0 + 8 * DD;
    #pragma unroll
    for (int nt = 0; nt < 8; nt++) {
        int col = nt * 8 + 2 * c;
        *(__half2*)(O + r0 + col) =
            __floats2half2_rn(acc[nt][0] * inv0, acc[nt][1] * inv0);
        *(__half2*)(O + r1 + col) =
            __floats2half2_rn(acc[nt][2] * inv1, acc[nt][3] * inv1);
    }
}

// ---------------- launch ---------------------------------------------------
extern "C" void kernel_launch(void* const* d_in, const int* in_sizes, int n_in,
                              void* d_out, int out_size)
{
    const float* hidden = (const float*)d_in[0];
    const int*   mask   = (const int*)d_in[1];
    const float* wq = (const float*)d_in[2];
    const float* bq = (const float*)d_in[3];
    const float* wk = (const float*)d_in[4];
    const float* bk = (const float*)d_in[5];
    const float* wv = (const float*)d_in[6];
    const float* bv = (const float*)d_in[7];
    const float* wo = (const float*)d_in[8];
    const float* bo = (const float*)d_in[9];
    const float* w1 = (const float*)d_in[10];
    const float* b1 = (const float*)d_in[11];
    const float* w2 = (const float*)d_in[12];
    const float* b2 = (const float*)d_in[13];
    const float* ln1_g = (const float*)d_in[14];
    const float* ln1_b = (const float*)d_in[15];
    const float* ln2_g = (const float*)d_in[16];
    const float* ln2_b = (const float*)d_in[17];
    float* out = (float*)d_out;

    __half *ln, *qkv, *attn, *f1, *wqkvh, *woh, *w1h, *w2h;
    float *h1, *bqkv;
    cudaGetSymbolAddress((void**)&ln,    g_ln);
    cudaGetSymbolAddress((void**)&qkv,   g_qkv);
    cudaGetSymbolAddress((void**)&attn,  g_attn);
    cudaGetSymbolAddress((void**)&h1,    g_h1);
    cudaGetSymbolAddress((void**)&f1,    g_f1);
    cudaGetSymbolAddress((void**)&wqkvh, g_wqkv);
    cudaGetSymbolAddress((void**)&bqkv,  g_bqkv);
    cudaGetSymbolAddress((void**)&woh,   g_wo);
    cudaGetSymbolAddress((void**)&w1h,   g_w1);
    cudaGetSymbolAddress((void**)&w2h,   g_w2);

    cudaFuncSetAttribute(flash_f16,
                         cudaFuncAttributeMaxDynamicSharedMemorySize, FLASH_SMEM);
    cudaFuncSetAttribute(gemm_f16<1>,
                         cudaFuncAttributeMaxDynamicSharedMemorySize, GEMM_SMEM);
    cudaFuncSetAttribute(gemm_f16<2>,
                         cudaFuncAttributeMaxDynamicSharedMemorySize, GEMM_SMEM);
    cudaFuncSetAttribute(gemm_f16<3>,
                         cudaFuncAttributeMaxDynamicSharedMemorySize, GEMM_SMEM);

    // one fused pack launch
    pack_all<<<(unsigned)PACK_BLOCKS, 256>>>(wq, wk, wv, wo, w1, w2, bq, bk, bv,
                                             wqkvh, woh, w1h, w2h, bqkv);

    // 1) LN1 (warp-per-row)
    ln_kernel<<<NROWS / 8, 256>>>(hidden, ln1_g, ln1_b, ln);

    // 2) fused QKV projection -> fp16
    dim3 gQKV(NQKV / 128, NROWS / 128);
    gemm_f16<3><<<gQKV, 256, GEMM_SMEM>>>(ln, wqkvh, bqkv, nullptr, qkv,
                                          NROWS, DD, NQKV);

    // 3) attention
    flash_f16<<<dim3(SS / 128, HH, BB), 256, FLASH_SMEM>>>(
        qkv, qkv + DD, qkv + 2 * DD, NQKV, mask, attn);

    // 4) output projection + residual -> fp32
    dim3 gD(DD / 128, NROWS / 128);
    gemm_f16<2><<<gD, 256, GEMM_SMEM>>>(attn, woh, bo, hidden, h1, NROWS, DD, DD);

    // 5) LN2
    ln_kernel<<<NROWS / 8, 256>>>(h1, ln2_g, ln2_b, ln);

    // 6) FFN
    dim3 gF(DFF / 128, NROWS / 128);
    gemm_f16<1><<<gF, 256, GEMM_SMEM>>>(ln, w1h, b1, nullptr, f1, NROWS, DD, DFF);
    gemm_f16<2><<<gD, 256, GEMM_SMEM>>>(f1, w2h, b2, h1, out, NROWS, DFF, DD);
}

// round 10
// speedup vs baseline: 1.0945x; 1.0062x over previous
#include <cuda_runtime.h>
#include <cuda_fp16.h>
#include <math.h>
#include <stdint.h>

#define BB 2
#define SS 2048
#define DD 1024
#define HH 16
#define DHD 64
#define DFF 4096
#define NROWS (BB * SS)
#define NQKV 3072

// ---------------- scratch (device globals; no allocation) ----------------
__device__ __half g_ln[NROWS * DD];
__device__ __half g_qkv[NROWS * NQKV];
__device__ __half g_attn[NROWS * DD];
__device__ float  g_h1[NROWS * DD];
__device__ __half g_f1[NROWS * DFF];
__device__ __half g_wqkv[DD * NQKV];
__device__ float  g_bqkv[NQKV];
__device__ __half g_wo[DD * DD];
__device__ __half g_w1[DD * DFF];
__device__ __half g_w2[DFF * DD];

// ---------------- helpers --------------------------------------------------
__device__ __forceinline__ uint32_t smem_u32(const void* p) {
    uint32_t a;
    asm("{ .reg .u64 t; cvta.to.shared.u64 t, %1; cvt.u32.u64 %0, t; }" : "=r"(a) : "l"(p));
    return a;
}
__device__ __forceinline__ void cp16(void* dst_smem, const void* src) {
    uint32_t d;
    asm("{ .reg .u64 t; cvta.to.shared.u64 t, %1; cvt.u32.u64 %0, t; }"
        : "=r"(d) : "l"(dst_smem));
    asm volatile("cp.async.cg.shared.global [%0], [%1], 16;" :: "r"(d), "l"(src));
}
__device__ __forceinline__ void cp_commit() {
    asm volatile("cp.async.commit_group;");
}
template <int N>
__device__ __forceinline__ void cp_wait() {
    asm volatile("cp.async.wait_group %0;" :: "n"(N));
}
__device__ __forceinline__ void ldm_x4(uint32_t r[4], uint32_t addr) {
    asm volatile("ldmatrix.sync.aligned.m8n8.x4.shared.b16 {%0,%1,%2,%3}, [%4];"
        : "=r"(r[0]), "=r"(r[1]), "=r"(r[2]), "=r"(r[3]) : "r"(addr));
}
__device__ __forceinline__ void ldm_x4t(uint32_t r[4], uint32_t addr) {
    asm volatile("ldmatrix.sync.aligned.m8n8.x4.trans.shared.b16 {%0,%1,%2,%3}, [%4];"
        : "=r"(r[0]), "=r"(r[1]), "=r"(r[2]), "=r"(r[3]) : "r"(addr));
}
__device__ __forceinline__ void mma16(float c[4], const uint32_t a[4], const uint32_t b[2]) {
    asm volatile(
        "mma.sync.aligned.m16n8k16.row.col.f32.f16.f16.f32 "
        "{%0,%1,%2,%3}, {%4,%5,%6,%7}, {%8,%9}, {%0,%1,%2,%3};"
        : "+f"(c[0]), "+f"(c[1]), "+f"(c[2]), "+f"(c[3])
        : "r"(a[0]), "r"(a[1]), "r"(a[2]), "r"(a[3]), "r"(b[0]), "r"(b[1]));
}
__device__ __forceinline__ uint32_t packh2(float lo, float hi) {
    __half2 h = __floats2half2_rn(lo, hi);
    return *(uint32_t*)&h;
}
__device__ __forceinline__ float ex2f(float x) {
    float r;
    asm("ex2.approx.f32 %0, %1;" : "=f"(r) : "f"(x));
    return r;
}
__device__ __forceinline__ float gelu_tanh_f(float h) {
    const float c = 0.7978845608028654f;
    float u = c * (h + 0.044715f * h * h * h);
    return 0.5f * h * (1.0f + tanhf(u));
}

// ---------------- ONE fused pack kernel (all weights + biases) -------------
#define NW (DD * DD / 4)
#define NF (DD * DFF / 4)
__global__ void __launch_bounds__(256) pack_all(
    const float* __restrict__ wq, const float* __restrict__ wk,
    const float* __restrict__ wv, const float* __restrict__ wo,
    const float* __restrict__ w1, const float* __restrict__ w2,
    const float* __restrict__ bq, const float* __restrict__ bk,
    const float* __restrict__ bv,
    __half* __restrict__ wqkv, __half* __restrict__ woh,
    __half* __restrict__ w1h, __half* __restrict__ w2h,
    float* __restrict__ bqkv)
{
    long i = (long)blockIdx.x * 256 + threadIdx.x;
    if (i < 3L * NW) {
        const float* src = (i < NW) ? wq : (i < 2L * NW) ? wk : wv;
        int coff = (i < NW) ? 0 : (i < 2L * NW) ? DD : 2 * DD;
        long ii = i % NW;
        int row = (int)(ii >> 8), c4 = ((int)ii & 255) << 2;
        float4 v = ((const float4*)src)[ii];
        __half2* o = (__half2*)(wqkv + (size_t)row * NQKV + coff + c4);
        o[0] = __floats2half2_rn(v.x, v.y);
        o[1] = __floats2half2_rn(v.z, v.w);
    } else if (i < 4L * NW) {
        long ii = i - 3L * NW;
        float4 v = ((const float4*)wo)[ii];
        __half2* o = (__half2*)(woh + ii * 4);
        o[0] = __floats2half2_rn(v.x, v.y);
        o[1] = __floats2half2_rn(v.z, v.w);
    } else if (i < 4L * NW + NF) {
        long ii = i - 4L * NW;
        float4 v = ((const float4*)w1)[ii];
        __half2* o = (__half2*)(w1h + ii * 4);
        o[0] = __floats2half2_rn(v.x, v.y);
        o[1] = __floats2half2_rn(v.z, v.w);
    } else if (i < 4L * NW + 2L * NF) {
        long ii = i - 4L * NW - NF;
        float4 v = ((const float4*)w2)[ii];
        __half2* o = (__half2*)(w2h + ii * 4);
        o[0] = __floats2half2_rn(v.x, v.y);
        o[1] = __floats2half2_rn(v.z, v.w);
    } else {
        long ii = i - 4L * NW - 2L * NF;
        if (ii < 768) {
            int j = (int)ii * 4;
            const float* src = (j < DD) ? bq : (j < 2 * DD) ? bk : bv;
            int jj = j & (DD - 1);
            *(float4*)(bqkv + j) = *(const float4*)(src + jj);
        }
    }
}
#define PACK_BLOCKS ((4L * NW + 2L * NF + 768 + 255) / 256)

// ---------------- LayerNorm: one warp per row, shfl-only -------------------
__global__ void __launch_bounds__(256) ln_kernel(
    const float* __restrict__ x, const float* __restrict__ gw,
    const float* __restrict__ bw, __half* __restrict__ y)
{
    int warp = threadIdx.x >> 5, lane = threadIdx.x & 31;
    int row = blockIdx.x * 8 + warp;
    const float4* xr = (const float4*)(x + (size_t)row * DD);

    float4 v[8];
    float s = 0.f, ss = 0.f;
    #pragma unroll
    for (int i = 0; i < 8; i++) {
        v[i] = xr[lane + i * 32];
        s  += v[i].x + v[i].y + v[i].z + v[i].w;
        ss += v[i].x * v[i].x + v[i].y * v[i].y + v[i].z * v[i].z + v[i].w * v[i].w;
    }
    #pragma unroll
    for (int o = 16; o; o >>= 1) {
        s  += __shfl_xor_sync(0xffffffffu, s,  o);
        ss += __shfl_xor_sync(0xffffffffu, ss, o);
    }
    float mean = s * (1.0f / DD);
    float var  = (ss - s * s * (1.0f / DD)) * (1.0f / (DD - 1));
    var = fmaxf(var, 0.f);
    float rd = 1.0f / (sqrtf(var) + 1e-6f);

    __half2* yo = (__half2*)(y + (size_t)row * DD);
    #pragma unroll
    for (int i = 0; i < 8; i++) {
        float4 g4 = ((const float4*)gw)[lane + i * 32];
        float4 b4 = ((const float4*)bw)[lane + i * 32];
        yo[2 * (lane + i * 32)] =
            __floats2half2_rn(g4.x * (v[i].x - mean) * rd + b4.x,
                              g4.y * (v[i].y - mean) * rd + b4.y);
        yo[2 * (lane + i * 32) + 1] =
            __floats2half2_rn(g4.z * (v[i].z - mean) * rd + b4.z,
                              g4.w * (v[i].w - mean) * rd + b4.w);
    }
}

// ---------------- fp16 mma GEMM (128x128x32, 8 warps, 2 CTA/SM) -------------
#define TKH 32
#define ASTRH 40
#define BSTRH 136
#define A_TILE_H (128 * ASTRH)
#define B_TILE_H (TKH * BSTRH)
#define STAGE_H (A_TILE_H + B_TILE_H)
#define NSTG 4
#define GEMM_SMEM (NSTG * STAGE_H * 2)

// EPI: 1 = bias+gelu -> fp16 out, 2 = bias+residual -> fp32 out,
//      3 = bias -> fp16 out
template <int EPI>
__global__ void __launch_bounds__(256, 2) gemm_f16(
    const __half* __restrict__ A, const __half* __restrict__ W,
    const float* __restrict__ bias, const float* __restrict__ R,
    void* __restrict__ Cv, int M, int K, int N)
{
    extern __shared__ __half smh[];
    uint32_t sbase = smem_u32(smh);
    int t = threadIdx.x;
    int m0 = blockIdx.y * 128, n0 = blockIdx.x * 128;
    int nkt = K >> 5;

    auto load_tile = [&](int stg, int kt) {
        __half* As = smh + stg * STAGE_H;
        __half* Bs = As + A_TILE_H;
        int k0 = kt * TKH;
        #pragma unroll
        for (int i = 0; i < 2; i++) {
            int id = t + i * 256;
            int row = id >> 2, c8 = (id & 3) << 3;
            cp16(As + row * ASTRH + c8, A + (size_t)(m0 + row) * K + k0 + c8);
        }
        #pragma unroll
        for (int i = 0; i < 2; i++) {
            int id = t + i * 256;
            int row = id >> 4, c8 = (id & 15) << 3;
            cp16(Bs + row * BSTRH + c8, W + (size_t)(k0 + row) * N + n0 + c8);
        }
    };

    float acc[4][4][4];
    #pragma unroll
    for (int mt = 0; mt < 4; mt++)
        #pragma unroll
        for (int nt = 0; nt < 4; nt++)
            #pragma unroll
            for (int i = 0; i < 4; i++) acc[mt][nt][i] = 0.f;

    int lane = t & 31, wid = t >> 5;
    int warpM = wid >> 2, warpN = wid & 3;
    int g = lane >> 2, c = lane & 3;
    int arow_l = lane & 15;
    int acol_l = (lane >> 4) << 3;
    int mat = lane >> 3, lr = lane & 7;
    int bko = ((mat & 1) << 3) + lr;
    int bno = (mat >> 1) << 3;

    #pragma unroll
    for (int s = 0; s < NSTG - 1; s++) { load_tile(s, s); cp_commit(); }

    for (int kt = 0; kt < nkt; kt++) {
        cp_wait<NSTG - 2>();
        __syncthreads();

        int nx = kt + NSTG - 1;
        if (nx < nkt) load_tile(nx & (NSTG - 1), nx);
        cp_commit();

        uint32_t As_u = sbase + (uint32_t)((kt & (NSTG - 1)) * STAGE_H) * 2;
        uint32_t Bs_u = As_u + A_TILE_H * 2;

        #pragma unroll
        for (int ks = 0; ks < 2; ks++) {
            uint32_t af[4][4];
            #pragma unroll
            for (int mt = 0; mt < 4; mt++)
                ldm_x4(af[mt], As_u +
                    ((uint32_t)((warpM * 64 + mt * 16 + arow_l) * ASTRH
                                + ks * 16 + acol_l) << 1));
            uint32_t b4[2][4];
            #pragma unroll
            for (int p = 0; p < 2; p++) {
                int bk = ks * 16 + bko;
                int bn = warpN * 32 + p * 16 + bno;
                ldm_x4t(b4[p], Bs_u + ((uint32_t)(bk * BSTRH + bn) << 1));
            }
            #pragma unroll
            for (int mt = 0; mt < 4; mt++)
                #pragma unroll
                for (int nt = 0; nt < 4; nt++)
                    mma16(acc[mt][nt], af[mt], &b4[nt >> 1][(nt & 1) << 1]);
        }
    }

    int rbase = m0 + warpM * 64 + g;
    int cbase = n0 + warpN * 32 + 2 * c;

    #pragma unroll
    for (int nt = 0; nt < 4; nt++) {
        int col = cbase + nt * 8;
        float2 b2 = *(const float2*)(bias + col);
        #pragma unroll
        for (int mt = 0; mt < 4; mt++) {
            int r0 = rbase + mt * 16;
            float v0x = acc[mt][nt][0] + b2.x;
            float v0y = acc[mt][nt][1] + b2.y;
            float v1x = acc[mt][nt][2] + b2.x;
            float v1y = acc[mt][nt][3] + b2.y;
            if (EPI == 2) {
                float* C = (float*)Cv;
                float2 r0v = *(const float2*)(R + (size_t)r0 * N + col);
                float2 r1v = *(const float2*)(R + (size_t)(r0 + 8) * N + col);
                *(float2*)(C + (size_t)r0 * N + col) =
                    make_float2(v0x + r0v.x, v0y + r0v.y);
                *(float2*)(C + (size_t)(r0 + 8) * N + col) =
                    make_float2(v1x + r1v.x, v1y + r1v.y);
            } else {
                if (EPI == 1) {
                    v0x = gelu_tanh_f(v0x); v0y = gelu_tanh_f(v0y);
                    v1x = gelu_tanh_f(v1x); v1y = gelu_tanh_f(v1y);
                }
                __half* C = (__half*)Cv;
                *(__half2*)(C + (size_t)r0 * N + col) = __floats2half2_rn(v0x, v0y);
                *(__half2*)(C + (size_t)(r0 + 8) * N + col) = __floats2half2_rn(v1x, v1y);
            }
        }
    }
}

// ---------------- fp16 tensor-core flash attention ---------------------------
// 4 warps x 32 q-rows: K/V fragments loaded once per warp serve 2x MMAs
// (halves smem crossbar traffic vs 8x16 layout). 4-stage KV pipeline.
#define FQSTR 72
#define FQ_H (128 * FQSTR)
#define FKV_H (64 * FQSTR)
#define KOFF FQ_H
#define VOFF (FQ_H + 4 * FKV_H)
#define MOFF_BYTES ((FQ_H + 8 * FKV_H) * 2)
#define FLASH_SMEM (MOFF_BYTES + 4 * 64 * 4 + 16)
#define QSCALE 0.1803368801111204f   /* 0.125 * log2(e) */
#define MBIAS  (-1.44269504e9f)      /* -1e9 * log2(e)  */

__global__ void __launch_bounds__(128, 2) flash_f16(
    const __half* __restrict__ Q, const __half* __restrict__ Kg,
    const __half* __restrict__ Vg, int ldq, const int* __restrict__ mask,
    __half* __restrict__ O)
{
    extern __shared__ __half smh[];
    uint32_t sbase = smem_u32(smh);
    int* mksm = (int*)((char*)smh + MOFF_BYTES);
    int t = threadIdx.x;
    int lane = t & 31, wid = t >> 5;
    int g = lane >> 2, c = lane & 3;
    int q0 = blockIdx.x * 128;
    int h = blockIdx.y, b = blockIdx.z;
    size_t baseQ = ((size_t)(b * SS + q0)) * ldq + h * DHD;

    auto load_kv = [&](int kt, int s) {
        size_t baseK = ((size_t)(b * SS + kt * 64)) * ldq + h * DHD;
        __half* Kb = smh + KOFF + s * FKV_H;
        __half* Vb = smh + VOFF + s * FKV_H;
        #pragma unroll
        for (int i = 0; i < 4; i++) {
            int id = t + i * 128;
            int row = id >> 3, c8 = (id & 7) << 3;
            cp16(Kb + row * FQSTR + c8, Kg + baseK + (size_t)row * ldq + c8);
            cp16(Vb + row * FQSTR + c8, Vg + baseK + (size_t)row * ldq + c8);
        }
        if (t < 16) cp16(mksm + s * 64 + t * 4, mask + b * SS + kt * 64 + t * 4);
    };

    load_kv(0, 0);
    #pragma unroll
    for (int i = 0; i < 8; i++) {
        int id = t + i * 128;
        int row = id >> 3, c8 = (id & 7) << 3;
        cp16(smh + row * FQSTR + c8, Q + baseQ + (size_t)row * ldq + c8);
    }
    cp_commit();
    load_kv(1, 1);
    cp_commit();
    load_kv(2, 2);
    cp_commit();

    cp_wait<2>();
    __syncthreads();

    int arow_l = lane & 15;
    int acol_l = (lane >> 4) << 3;
    int mat = lane >> 3, lr = lane & 7;
    // Q fragments: 2 m-tiles x 4 k-steps, scale folded in fp16
    uint32_t qf[2][4][4];
    int qb = wid * 32;
    {
        __half2 qs = __float2half2_rn(QSCALE);
        #pragma unroll
        for (int mt = 0; mt < 2; mt++)
            #pragma unroll
            for (int ks = 0; ks < 4; ks++) {
                ldm_x4(qf[mt][ks], sbase +
                    ((uint32_t)((qb + mt * 16 + arow_l) * FQSTR
                                + ks * 16 + acol_l) << 1));
                #pragma unroll
                for (int i = 0; i < 4; i++) {
                    __half2 hv = *(__half2*)&qf[mt][ks][i];
                    hv = __hmul2(hv, qs);
                    qf[mt][ks][i] = *(uint32_t*)&hv;
                }
            }
    }

    float m0[2], m1[2], l0[2], l1[2];
    #pragma unroll
    for (int mt = 0; mt < 2; mt++) {
        m0[mt] = -1e30f; m1[mt] = -1e30f; l0[mt] = 0.f; l1[mt] = 0.f;
    }
    float acc[2][8][4];
    #pragma unroll
    for (int mt = 0; mt < 2; mt++)
        #pragma unroll
        for (int nt = 0; nt < 8; nt++)
            #pragma unroll
            for (int i = 0; i < 4; i++) acc[mt][nt][i] = 0.f;

    uint32_t kfrag_base = sbase + ((uint32_t)(((mat >> 1) << 3) + lr) * FQSTR
                                   + ((mat & 1) << 3)) * 2 + KOFF * 2;
    uint32_t vfrag_base = sbase + ((uint32_t)((((mat & 1) << 3) + lr) * FQSTR)
                                   + (((mat >> 1) << 3))) * 2 + VOFF * 2;

    for (int kto = 0; kto < SS / 64; kto += 4) {
        #pragma unroll
        for (int st = 0; st < 4; st++) {
            int kt = kto + st;
            cp_wait<2>();
            __syncthreads();

            int nx = kt + 3;
            if (nx < SS / 64) load_kv(nx, nx & 3);
            cp_commit();

            const int* mk = mksm + st * 64;

            float sf[2][8][4];
            #pragma unroll
            for (int mt = 0; mt < 2; mt++)
                #pragma unroll
                for (int nt = 0; nt < 8; nt++)
                    #pragma unroll
                    for (int i = 0; i < 4; i++) sf[mt][nt][i] = 0.f;

            // S = Q K^T : one K-frag load serves both m-tiles
            #pragma unroll
            for (int ks = 0; ks < 4; ks++) {
                #pragma unroll
                for (int p = 0; p < 4; p++) {
                    uint32_t kb[4];
                    ldm_x4(kb, kfrag_base + (uint32_t)(st * FKV_H * 2)
                               + (uint32_t)((p * 16 * FQSTR + ks * 16) << 1));
                    #pragma unroll
                    for (int mt = 0; mt < 2; mt++) {
                        mma16(sf[mt][2 * p],     qf[mt][ks], kb);
                        mma16(sf[mt][2 * p + 1], qf[mt][ks], kb + 2);
                    }
                }
            }

            // online softmax per m-tile (rows g, g+8 within tile)
            #pragma unroll
            for (int mt = 0; mt < 2; mt++) {
                float mx0 = -1e30f, mx1 = -1e30f;
                #pragma unroll
                for (int nt = 0; nt < 8; nt++) {
                    float bia0 = mk[nt * 8 + 2 * c]     ? 0.f : MBIAS;
                    float bia1 = mk[nt * 8 + 2 * c + 1] ? 0.f : MBIAS;
                    sf[mt][nt][0] += bia0; sf[mt][nt][1] += bia1;
                    sf[mt][nt][2] += bia0; sf[mt][nt][3] += bia1;
                    mx0 = fmaxf(mx0, fmaxf(sf[mt][nt][0], sf[mt][nt][1]));
                    mx1 = fmaxf(mx1, fmaxf(sf[mt][nt][2], sf[mt][nt][3]));
                }
                mx0 = fmaxf(mx0, __shfl_xor_sync(0xffffffffu, mx0, 1));
                mx0 = fmaxf(mx0, __shfl_xor_sync(0xffffffffu, mx0, 2));
                mx1 = fmaxf(mx1, __shfl_xor_sync(0xffffffffu, mx1, 1));
                mx1 = fmaxf(mx1, __shfl_xor_sync(0xffffffffu, mx1, 2));

                float mn0 = fmaxf(m0[mt], mx0), mn1 = fmaxf(m1[mt], mx1);
                float al0 = ex2f(m0[mt] - mn0), al1 = ex2f(m1[mt] - mn1);
                m0[mt] = mn0; m1[mt] = mn1;

                float ps0 = 0.f, ps1 = 0.f;
                #pragma unroll
                for (int nt = 0; nt < 8; nt++) {
                    sf[mt][nt][0] = ex2f(sf[mt][nt][0] - mn0);
                    sf[mt][nt][1] = ex2f(sf[mt][nt][1] - mn0);
                    sf[mt][nt][2] = ex2f(sf[mt][nt][2] - mn1);
                    sf[mt][nt][3] = ex2f(sf[mt][nt][3] - mn1);
                    ps0 += sf[mt][nt][0] + sf[mt][nt][1];
                    ps1 += sf[mt][nt][2] + sf[mt][nt][3];
                }
                ps0 += __shfl_xor_sync(0xffffffffu, ps0, 1);
                ps0 += __shfl_xor_sync(0xffffffffu, ps0, 2);
                ps1 += __shfl_xor_sync(0xffffffffu, ps1, 1);
                ps1 += __shfl_xor_sync(0xffffffffu, ps1, 2);
                l0[mt] = l0[mt] * al0 + ps0;
                l1[mt] = l1[mt] * al1 + ps1;

                #pragma unroll
                for (int nt = 0; nt < 8; nt++) {
                    acc[mt][nt][0] *= al0; acc[mt][nt][1] *= al0;
                    acc[mt][nt][2] *= al1; acc[mt][nt][3] *= al1;
                }
            }

            // acc += P V : one V-frag load serves both m-tiles
            #pragma unroll
            for (int ks = 0; ks < 4; ks++) {
                uint32_t af[2][4];
                #pragma unroll
                for (int mt = 0; mt < 2; mt++) {
                    af[mt][0] = packh2(sf[mt][2 * ks][0],     sf[mt][2 * ks][1]);
                    af[mt][1] = packh2(sf[mt][2 * ks][2],     sf[mt][2 * ks][3]);
                    af[mt][2] = packh2(sf[mt][2 * ks + 1][0], sf[mt][2 * ks + 1][1]);
                    af[mt][3] = packh2(sf[mt][2 * ks + 1][2], sf[mt][2 * ks + 1][3]);
                }
                #pragma unroll
                for (int p = 0; p < 4; p++) {
                    uint32_t vb[4];
                    ldm_x4t(vb, vfrag_base + (uint32_t)(st * FKV_H * 2)
                                + (uint32_t)((ks * 16 * FQSTR + p * 16) << 1));
                    #pragma unroll
                    for (int mt = 0; mt < 2; mt++) {
                        mma16(acc[mt][2 * p],     af[mt], vb);
                        mma16(acc[mt][2 * p + 1], af[mt], vb + 2);
                    }
                }
            }
        }
    }

    #pragma unroll
    for (int mt = 0; mt < 2; mt++) {
        float inv0 = 1.f / l0[mt], inv1 = 1.f / l1[mt];
        size_t r0 = ((size_t)(b * SS + q0 + qb + mt * 16 + g)) * DD + h * DHD;
        size_t r1 = r0 + 8 * DD;
        #pragma unroll
        for (int nt = 0; nt < 8; nt++) {
            int col = nt * 8 + 2 * c;
            *(__half2*)(O + r0 + col) =
                __floats2half2_rn(acc[mt][nt][0] * inv0, acc[mt][nt][1] * inv0);
            *(__half2*)(O + r1 + col) =
                __floats2half2_rn(acc[mt][nt][2] * inv1, acc[mt][nt][3] * inv1);
        }
    }
}

// ---------------- launch ---------------------------------------------------
extern "C" void kernel_launch(void* const* d_in, const int* in_sizes, int n_in,
                              void* d_out, int out_size)
{
    const float* hidden = (const float*)d_in[0];
    const int*   mask   = (const int*)d_in[1];
    const float* wq = (const float*)d_in[2];
    const float* bq = (const float*)d_in[3];
    const float* wk = (const float*)d_in[4];
    const float* bk = (const float*)d_in[5];
    const float* wv = (const float*)d_in[6];
    const float* bv = (const float*)d_in[7];
    const float* wo = (const float*)d_in[8];
    const float* bo = (const float*)d_in[9];
    const float* w1 = (const float*)d_in[10];
    const float* b1 = (const float*)d_in[11];
    const float* w2 = (const float*)d_in[12];
    const float* b2 = (const float*)d_in[13];
    const float* ln1_g = (const float*)d_in[14];
    const float* ln1_b = (const float*)d_in[15];
    const float* ln2_g = (const float*)d_in[16];
    const float* ln2_b = (const float*)d_in[17];
    float* out = (float*)d_out;

    __half *ln, *qkv, *attn, *f1, *wqkvh, *woh, *w1h, *w2h;
    float *h1, *bqkv;
    cudaGetSymbolAddress((void**)&ln,    g_ln);
    cudaGetSymbolAddress((void**)&qkv,   g_qkv);
    cudaGetSymbolAddress((void**)&attn,  g_attn);
    cudaGetSymbolAddress((void**)&h1,    g_h1);
    cudaGetSymbolAddress((void**)&f1,    g_f1);
    cudaGetSymbolAddress((void**)&wqkvh, g_wqkv);
    cudaGetSymbolAddress((void**)&bqkv,  g_bqkv);
    cudaGetSymbolAddress((void**)&woh,   g_wo);
    cudaGetSymbolAddress((void**)&w1h,   g_w1);
    cudaGetSymbolAddress((void**)&w2h,   g_w2);

    cudaFuncSetAttribute(flash_f16,
                         cudaFuncAttributeMaxDynamicSharedMemorySize, FLASH_SMEM);
    cudaFuncSetAttribute(gemm_f16<1>,
                         cudaFuncAttributeMaxDynamicSharedMemorySize, GEMM_SMEM);
    cudaFuncSetAttribute(gemm_f16<2>,
                         cudaFuncAttributeMaxDynamicSharedMemorySize, GEMM_SMEM);
    cudaFuncSetAttribute(gemm_f16<3>,
                         cudaFuncAttributeMaxDynamicSharedMemorySize, GEMM_SMEM);

    // one fused pack launch
    pack_all<<<(unsigned)PACK_BLOCKS, 256>>>(wq, wk, wv, wo, w1, w2, bq, bk, bv,
                                             wqkvh, woh, w1h, w2h, bqkv);

    // 1) LN1 (warp-per-row)
    ln_kernel<<<NROWS / 8, 256>>>(hidden, ln1_g, ln1_b, ln);

    // 2) fused QKV projection -> fp16
    dim3 gQKV(NQKV / 128, NROWS / 128);
    gemm_f16<3><<<gQKV, 256, GEMM_SMEM>>>(ln, wqkvh, bqkv, nullptr, qkv,
                                          NROWS, DD, NQKV);

    // 3) attention (4-warp CTA, 128 threads)
    flash_f16<<<dim3(SS / 128, HH, BB), 128, FLASH_SMEM>>>(
        qkv, qkv + DD, qkv + 2 * DD, NQKV, mask, attn);

    // 4) output projection + residual -> fp32
    dim3 gD(DD / 128, NROWS / 128);
    gemm_f16<2><<<gD, 256, GEMM_SMEM>>>(attn, woh, bo, hidden, h1, NROWS, DD, DD);

    // 5) LN2
    ln_kernel<<<NROWS / 8, 256>>>(h1, ln2_g, ln2_b, ln);

    // 6) FFN
    dim3 gF(DFF / 128, NROWS / 128);
    gemm_f16<1><<<gF, 256, GEMM_SMEM>>>(ln, w1h, b1, nullptr, f1, NROWS, DD, DFF);
    gemm_f16<2><<<gD, 256, GEMM_SMEM>>>(f1, w2h, b2, h1, out, NROWS, DFF, DD);
}

// round 11
// speedup vs baseline: 1.1484x; 1.0493x over previous
#include <cuda_runtime.h>
#include <cuda_fp16.h>
#include <math.h>
#include <stdint.h>

#define BB 2
#define SS 2048
#define DD 1024
#define HH 16
#define DHD 64
#define DFF 4096
#define NROWS (BB * SS)
#define NQKV 3072

// ---------------- scratch (device globals; no allocation) ----------------
__device__ __half g_ln[NROWS * DD];
__device__ __half g_qkv[NROWS * NQKV];
__device__ __half g_attn[NROWS * DD];
__device__ float  g_h1[NROWS * DD];
__device__ __half g_f1[NROWS * DFF];
__device__ __half g_wqkv[DD * NQKV];
__device__ float  g_bqkv[NQKV];
__device__ __half g_wo[DD * DD];
__device__ __half g_w1[DD * DFF];
__device__ __half g_w2[DFF * DD];

// ---------------- helpers --------------------------------------------------
__device__ __forceinline__ uint32_t smem_u32(const void* p) {
    uint32_t a;
    asm("{ .reg .u64 t; cvta.to.shared.u64 t, %1; cvt.u32.u64 %0, t; }" : "=r"(a) : "l"(p));
    return a;
}
__device__ __forceinline__ void cp16(void* dst_smem, const void* src) {
    uint32_t d;
    asm("{ .reg .u64 t; cvta.to.shared.u64 t, %1; cvt.u32.u64 %0, t; }"
        : "=r"(d) : "l"(dst_smem));
    asm volatile("cp.async.cg.shared.global [%0], [%1], 16;" :: "r"(d), "l"(src));
}
__device__ __forceinline__ void cp_commit() {
    asm volatile("cp.async.commit_group;");
}
template <int N>
__device__ __forceinline__ void cp_wait() {
    asm volatile("cp.async.wait_group %0;" :: "n"(N));
}
__device__ __forceinline__ void ldm_x4(uint32_t r[4], uint32_t addr) {
    asm volatile("ldmatrix.sync.aligned.m8n8.x4.shared.b16 {%0,%1,%2,%3}, [%4];"
        : "=r"(r[0]), "=r"(r[1]), "=r"(r[2]), "=r"(r[3]) : "r"(addr));
}
__device__ __forceinline__ void ldm_x4t(uint32_t r[4], uint32_t addr) {
    asm volatile("ldmatrix.sync.aligned.m8n8.x4.trans.shared.b16 {%0,%1,%2,%3}, [%4];"
        : "=r"(r[0]), "=r"(r[1]), "=r"(r[2]), "=r"(r[3]) : "r"(addr));
}
__device__ __forceinline__ void mma16(float c[4], const uint32_t a[4], const uint32_t b[2]) {
    asm volatile(
        "mma.sync.aligned.m16n8k16.row.col.f32.f16.f16.f32 "
        "{%0,%1,%2,%3}, {%4,%5,%6,%7}, {%8,%9}, {%0,%1,%2,%3};"
        : "+f"(c[0]), "+f"(c[1]), "+f"(c[2]), "+f"(c[3])
        : "r"(a[0]), "r"(a[1]), "r"(a[2]), "r"(a[3]), "r"(b[0]), "r"(b[1]));
}
__device__ __forceinline__ uint32_t packh2(float lo, float hi) {
    __half2 h = __floats2half2_rn(lo, hi);
    return *(uint32_t*)&h;
}
__device__ __forceinline__ float ex2f(float x) {
    float r;
    asm("ex2.approx.f32 %0, %1;" : "=f"(r) : "f"(x));
    return r;
}
__device__ __forceinline__ float gelu_tanh_f(float h) {
    const float c = 0.7978845608028654f;
    float u = c * (h + 0.044715f * h * h * h);
    return 0.5f * h * (1.0f + tanhf(u));
}

// ---------------- ONE fused pack kernel (all weights + biases) -------------
#define NW (DD * DD / 4)
#define NF (DD * DFF / 4)
__global__ void __launch_bounds__(256) pack_all(
    const float* __restrict__ wq, const float* __restrict__ wk,
    const float* __restrict__ wv, const float* __restrict__ wo,
    const float* __restrict__ w1, const float* __restrict__ w2,
    const float* __restrict__ bq, const float* __restrict__ bk,
    const float* __restrict__ bv,
    __half* __restrict__ wqkv, __half* __restrict__ woh,
    __half* __restrict__ w1h, __half* __restrict__ w2h,
    float* __restrict__ bqkv)
{
    long i = (long)blockIdx.x * 256 + threadIdx.x;
    if (i < 3L * NW) {
        const float* src = (i < NW) ? wq : (i < 2L * NW) ? wk : wv;
        int coff = (i < NW) ? 0 : (i < 2L * NW) ? DD : 2 * DD;
        long ii = i % NW;
        int row = (int)(ii >> 8), c4 = ((int)ii & 255) << 2;
        float4 v = ((const float4*)src)[ii];
        __half2* o = (__half2*)(wqkv + (size_t)row * NQKV + coff + c4);
        o[0] = __floats2half2_rn(v.x, v.y);
        o[1] = __floats2half2_rn(v.z, v.w);
    } else if (i < 4L * NW) {
        long ii = i - 3L * NW;
        float4 v = ((const float4*)wo)[ii];
        __half2* o = (__half2*)(woh + ii * 4);
        o[0] = __floats2half2_rn(v.x, v.y);
        o[1] = __floats2half2_rn(v.z, v.w);
    } else if (i < 4L * NW + NF) {
        long ii = i - 4L * NW;
        float4 v = ((const float4*)w1)[ii];
        __half2* o = (__half2*)(w1h + ii * 4);
        o[0] = __floats2half2_rn(v.x, v.y);
        o[1] = __floats2half2_rn(v.z, v.w);
    } else if (i < 4L * NW + 2L * NF) {
        long ii = i - 4L * NW - NF;
        float4 v = ((const float4*)w2)[ii];
        __half2* o = (__half2*)(w2h + ii * 4);
        o[0] = __floats2half2_rn(v.x, v.y);
        o[1] = __floats2half2_rn(v.z, v.w);
    } else {
        long ii = i - 4L * NW - 2L * NF;
        if (ii < 768) {
            int j = (int)ii * 4;
            const float* src = (j < DD) ? bq : (j < 2 * DD) ? bk : bv;
            int jj = j & (DD - 1);
            *(float4*)(bqkv + j) = *(const float4*)(src + jj);
        }
    }
}
#define PACK_BLOCKS ((4L * NW + 2L * NF + 768 + 255) / 256)

// ---------------- LayerNorm: one warp per row, shfl-only -------------------
__global__ void __launch_bounds__(256) ln_kernel(
    const float* __restrict__ x, const float* __restrict__ gw,
    const float* __restrict__ bw, __half* __restrict__ y)
{
    int warp = threadIdx.x >> 5, lane = threadIdx.x & 31;
    int row = blockIdx.x * 8 + warp;
    const float4* xr = (const float4*)(x + (size_t)row * DD);

    float4 v[8];
    float s = 0.f, ss = 0.f;
    #pragma unroll
    for (int i = 0; i < 8; i++) {
        v[i] = xr[lane + i * 32];
        s  += v[i].x + v[i].y + v[i].z + v[i].w;
        ss += v[i].x * v[i].x + v[i].y * v[i].y + v[i].z * v[i].z + v[i].w * v[i].w;
    }
    #pragma unroll
    for (int o = 16; o; o >>= 1) {
        s  += __shfl_xor_sync(0xffffffffu, s,  o);
        ss += __shfl_xor_sync(0xffffffffu, ss, o);
    }
    float mean = s * (1.0f / DD);
    float var  = (ss - s * s * (1.0f / DD)) * (1.0f / (DD - 1));
    var = fmaxf(var, 0.f);
    float rd = 1.0f / (sqrtf(var) + 1e-6f);

    __half2* yo = (__half2*)(y + (size_t)row * DD);
    #pragma unroll
    for (int i = 0; i < 8; i++) {
        float4 g4 = ((const float4*)gw)[lane + i * 32];
        float4 b4 = ((const float4*)bw)[lane + i * 32];
        yo[2 * (lane + i * 32)] =
            __floats2half2_rn(g4.x * (v[i].x - mean) * rd + b4.x,
                              g4.y * (v[i].y - mean) * rd + b4.y);
        yo[2 * (lane + i * 32) + 1] =
            __floats2half2_rn(g4.z * (v[i].z - mean) * rd + b4.z,
                              g4.w * (v[i].w - mean) * rd + b4.w);
    }
}

// ---------------- fp16 mma GEMM (128x128x32, 4 warps x 64x64, 2 CTA/SM) ----
#define TKH 32
#define ASTRH 40
#define BSTRH 136
#define A_TILE_H (128 * ASTRH)
#define B_TILE_H (TKH * BSTRH)
#define STAGE_H (A_TILE_H + B_TILE_H)
#define NSTG 4
#define GEMM_SMEM (NSTG * STAGE_H * 2)

// EPI: 1 = bias+gelu -> fp16 out, 2 = bias+residual -> fp32 out,
//      3 = bias -> fp16 out
template <int EPI>
__global__ void __launch_bounds__(128, 2) gemm_f16(
    const __half* __restrict__ A, const __half* __restrict__ W,
    const float* __restrict__ bias, const float* __restrict__ R,
    void* __restrict__ Cv, int M, int K, int N)
{
    extern __shared__ __half smh[];
    uint32_t sbase = smem_u32(smh);
    int t = threadIdx.x;
    int m0 = blockIdx.y * 128, n0 = blockIdx.x * 128;
    int nkt = K >> 5;

    auto load_tile = [&](int stg, int kt) {
        __half* As = smh + stg * STAGE_H;
        __half* Bs = As + A_TILE_H;
        int k0 = kt * TKH;
        #pragma unroll
        for (int i = 0; i < 4; i++) {
            int id = t + i * 128;
            int row = id >> 2, c8 = (id & 3) << 3;
            cp16(As + row * ASTRH + c8, A + (size_t)(m0 + row) * K + k0 + c8);
        }
        #pragma unroll
        for (int i = 0; i < 4; i++) {
            int id = t + i * 128;
            int row = id >> 4, c8 = (id & 15) << 3;
            cp16(Bs + row * BSTRH + c8, W + (size_t)(k0 + row) * N + n0 + c8);
        }
    };

    float acc[4][8][4];
    #pragma unroll
    for (int mt = 0; mt < 4; mt++)
        #pragma unroll
        for (int nt = 0; nt < 8; nt++)
            #pragma unroll
            for (int i = 0; i < 4; i++) acc[mt][nt][i] = 0.f;

    int lane = t & 31, wid = t >> 5;
    int warpM = wid >> 1, warpN = wid & 1;
    int g = lane >> 2, c = lane & 3;
    int arow_l = lane & 15;
    int acol_l = (lane >> 4) << 3;
    int mat = lane >> 3, lr = lane & 7;
    int bko = ((mat & 1) << 3) + lr;
    int bno = (mat >> 1) << 3;

    #pragma unroll
    for (int s = 0; s < NSTG - 1; s++) { load_tile(s, s); cp_commit(); }

    for (int kt = 0; kt < nkt; kt++) {
        cp_wait<NSTG - 2>();
        __syncthreads();

        int nx = kt + NSTG - 1;
        if (nx < nkt) load_tile(nx & (NSTG - 1), nx);
        cp_commit();

        uint32_t As_u = sbase + (uint32_t)((kt & (NSTG - 1)) * STAGE_H) * 2;
        uint32_t Bs_u = As_u + A_TILE_H * 2;

        #pragma unroll
        for (int ks = 0; ks < 2; ks++) {
            uint32_t af[4][4];
            #pragma unroll
            for (int mt = 0; mt < 4; mt++)
                ldm_x4(af[mt], As_u +
                    ((uint32_t)((warpM * 64 + mt * 16 + arow_l) * ASTRH
                                + ks * 16 + acol_l) << 1));
            uint32_t b4[4][4];
            #pragma unroll
            for (int p = 0; p < 4; p++) {
                int bk = ks * 16 + bko;
                int bn = warpN * 64 + p * 16 + bno;
                ldm_x4t(b4[p], Bs_u + ((uint32_t)(bk * BSTRH + bn) << 1));
            }
            #pragma unroll
            for (int mt = 0; mt < 4; mt++)
                #pragma unroll
                for (int nt = 0; nt < 8; nt++)
                    mma16(acc[mt][nt], af[mt], &b4[nt >> 1][(nt & 1) << 1]);
        }
    }

    int rbase = m0 + warpM * 64 + g;
    int cbase = n0 + warpN * 64 + 2 * c;

    #pragma unroll
    for (int nt = 0; nt < 8; nt++) {
        int col = cbase + nt * 8;
        float2 b2 = *(const float2*)(bias + col);
        #pragma unroll
        for (int mt = 0; mt < 4; mt++) {
            int r0 = rbase + mt * 16;
            float v0x = acc[mt][nt][0] + b2.x;
            float v0y = acc[mt][nt][1] + b2.y;
            float v1x = acc[mt][nt][2] + b2.x;
            float v1y = acc[mt][nt][3] + b2.y;
            if (EPI == 2) {
                float* C = (float*)Cv;
                float2 r0v = *(const float2*)(R + (size_t)r0 * N + col);
                float2 r1v = *(const float2*)(R + (size_t)(r0 + 8) * N + col);
                *(float2*)(C + (size_t)r0 * N + col) =
                    make_float2(v0x + r0v.x, v0y + r0v.y);
                *(float2*)(C + (size_t)(r0 + 8) * N + col) =
                    make_float2(v1x + r1v.x, v1y + r1v.y);
            } else {
                if (EPI == 1) {
                    v0x = gelu_tanh_f(v0x); v0y = gelu_tanh_f(v0y);
                    v1x = gelu_tanh_f(v1x); v1y = gelu_tanh_f(v1y);
                }
                __half* C = (__half*)Cv;
                *(__half2*)(C + (size_t)r0 * N + col) = __floats2half2_rn(v0x, v0y);
                *(__half2*)(C + (size_t)(r0 + 8) * N + col) = __floats2half2_rn(v1x, v1y);
            }
        }
    }
}

// ---------------- fp16 tensor-core flash attention ---------------------------
// 4 warps x 32 q-rows, 4-stage KV pipeline (round-10 config, kept).
#define FQSTR 72
#define FQ_H (128 * FQSTR)
#define FKV_H (64 * FQSTR)
#define KOFF FQ_H
#define VOFF (FQ_H + 4 * FKV_H)
#define MOFF_BYTES ((FQ_H + 8 * FKV_H) * 2)
#define FLASH_SMEM (MOFF_BYTES + 4 * 64 * 4 + 16)
#define QSCALE 0.1803368801111204f   /* 0.125 * log2(e) */
#define MBIAS  (-1.44269504e9f)      /* -1e9 * log2(e)  */

__global__ void __launch_bounds__(128, 2) flash_f16(
    const __half* __restrict__ Q, const __half* __restrict__ Kg,
    const __half* __restrict__ Vg, int ldq, const int* __restrict__ mask,
    __half* __restrict__ O)
{
    extern __shared__ __half smh[];
    uint32_t sbase = smem_u32(smh);
    int* mksm = (int*)((char*)smh + MOFF_BYTES);
    int t = threadIdx.x;
    int lane = t & 31, wid = t >> 5;
    int g = lane >> 2, c = lane & 3;
    int q0 = blockIdx.x * 128;
    int h = blockIdx.y, b = blockIdx.z;
    size_t baseQ = ((size_t)(b * SS + q0)) * ldq + h * DHD;

    auto load_kv = [&](int kt, int s) {
        size_t baseK = ((size_t)(b * SS + kt * 64)) * ldq + h * DHD;
        __half* Kb = smh + KOFF + s * FKV_H;
        __half* Vb = smh + VOFF + s * FKV_H;
        #pragma unroll
        for (int i = 0; i < 4; i++) {
            int id = t + i * 128;
            int row = id >> 3, c8 = (id & 7) << 3;
            cp16(Kb + row * FQSTR + c8, Kg + baseK + (size_t)row * ldq + c8);
            cp16(Vb + row * FQSTR + c8, Vg + baseK + (size_t)row * ldq + c8);
        }
        if (t < 16) cp16(mksm + s * 64 + t * 4, mask + b * SS + kt * 64 + t * 4);
    };

    load_kv(0, 0);
    #pragma unroll
    for (int i = 0; i < 8; i++) {
        int id = t + i * 128;
        int row = id >> 3, c8 = (id & 7) << 3;
        cp16(smh + row * FQSTR + c8, Q + baseQ + (size_t)row * ldq + c8);
    }
    cp_commit();
    load_kv(1, 1);
    cp_commit();
    load_kv(2, 2);
    cp_commit();

    cp_wait<2>();
    __syncthreads();

    int arow_l = lane & 15;
    int acol_l = (lane >> 4) << 3;
    int mat = lane >> 3, lr = lane & 7;
    uint32_t qf[2][4][4];
    int qb = wid * 32;
    {
        __half2 qs = __float2half2_rn(QSCALE);
        #pragma unroll
        for (int mt = 0; mt < 2; mt++)
            #pragma unroll
            for (int ks = 0; ks < 4; ks++) {
                ldm_x4(qf[mt][ks], sbase +
                    ((uint32_t)((qb + mt * 16 + arow_l) * FQSTR
                                + ks * 16 + acol_l) << 1));
                #pragma unroll
                for (int i = 0; i < 4; i++) {
                    __half2 hv = *(__half2*)&qf[mt][ks][i];
                    hv = __hmul2(hv, qs);
                    qf[mt][ks][i] = *(uint32_t*)&hv;
                }
            }
    }

    float m0[2], m1[2], l0[2], l1[2];
    #pragma unroll
    for (int mt = 0; mt < 2; mt++) {
        m0[mt] = -1e30f; m1[mt] = -1e30f; l0[mt] = 0.f; l1[mt] = 0.f;
    }
    float acc[2][8][4];
    #pragma unroll
    for (int mt = 0; mt < 2; mt++)
        #pragma unroll
        for (int nt = 0; nt < 8; nt++)
            #pragma unroll
            for (int i = 0; i < 4; i++) acc[mt][nt][i] = 0.f;

    uint32_t kfrag_base = sbase + ((uint32_t)(((mat >> 1) << 3) + lr) * FQSTR
                                   + ((mat & 1) << 3)) * 2 + KOFF * 2;
    uint32_t vfrag_base = sbase + ((uint32_t)((((mat & 1) << 3) + lr) * FQSTR)
                                   + (((mat >> 1) << 3))) * 2 + VOFF * 2;

    for (int kto = 0; kto < SS / 64; kto += 4) {
        #pragma unroll
        for (int st = 0; st < 4; st++) {
            int kt = kto + st;
            cp_wait<2>();
            __syncthreads();

            int nx = kt + 3;
            if (nx < SS / 64) load_kv(nx, nx & 3);
            cp_commit();

            const int* mk = mksm + st * 64;

            float sf[2][8][4];
            #pragma unroll
            for (int mt = 0; mt < 2; mt++)
                #pragma unroll
                for (int nt = 0; nt < 8; nt++)
                    #pragma unroll
                    for (int i = 0; i < 4; i++) sf[mt][nt][i] = 0.f;

            #pragma unroll
            for (int ks = 0; ks < 4; ks++) {
                #pragma unroll
                for (int p = 0; p < 4; p++) {
                    uint32_t kb[4];
                    ldm_x4(kb, kfrag_base + (uint32_t)(st * FKV_H * 2)
                               + (uint32_t)((p * 16 * FQSTR + ks * 16) << 1));
                    #pragma unroll
                    for (int mt = 0; mt < 2; mt++) {
                        mma16(sf[mt][2 * p],     qf[mt][ks], kb);
                        mma16(sf[mt][2 * p + 1], qf[mt][ks], kb + 2);
                    }
                }
            }

            #pragma unroll
            for (int mt = 0; mt < 2; mt++) {
                float mx0 = -1e30f, mx1 = -1e30f;
                #pragma unroll
                for (int nt = 0; nt < 8; nt++) {
                    float bia0 = mk[nt * 8 + 2 * c]     ? 0.f : MBIAS;
                    float bia1 = mk[nt * 8 + 2 * c + 1] ? 0.f : MBIAS;
                    sf[mt][nt][0] += bia0; sf[mt][nt][1] += bia1;
                    sf[mt][nt][2] += bia0; sf[mt][nt][3] += bia1;
                    mx0 = fmaxf(mx0, fmaxf(sf[mt][nt][0], sf[mt][nt][1]));
                    mx1 = fmaxf(mx1, fmaxf(sf[mt][nt][2], sf[mt][nt][3]));
                }
                mx0 = fmaxf(mx0, __shfl_xor_sync(0xffffffffu, mx0, 1));
                mx0 = fmaxf(mx0, __shfl_xor_sync(0xffffffffu, mx0, 2));
                mx1 = fmaxf(mx1, __shfl_xor_sync(0xffffffffu, mx1, 1));
                mx1 = fmaxf(mx1, __shfl_xor_sync(0xffffffffu, mx1, 2));

                float mn0 = fmaxf(m0[mt], mx0), mn1 = fmaxf(m1[mt], mx1);
                float al0 = ex2f(m0[mt] - mn0), al1 = ex2f(m1[mt] - mn1);
                m0[mt] = mn0; m1[mt] = mn1;

                float ps0 = 0.f, ps1 = 0.f;
                #pragma unroll
                for (int nt = 0; nt < 8; nt++) {
                    sf[mt][nt][0] = ex2f(sf[mt][nt][0] - mn0);
                    sf[mt][nt][1] = ex2f(sf[mt][nt][1] - mn0);
                    sf[mt][nt][2] = ex2f(sf[mt][nt][2] - mn1);
                    sf[mt][nt][3] = ex2f(sf[mt][nt][3] - mn1);
                    ps0 += sf[mt][nt][0] + sf[mt][nt][1];
                    ps1 += sf[mt][nt][2] + sf[mt][nt][3];
                }
                ps0 += __shfl_xor_sync(0xffffffffu, ps0, 1);
                ps0 += __shfl_xor_sync(0xffffffffu, ps0, 2);
                ps1 += __shfl_xor_sync(0xffffffffu, ps1, 1);
                ps1 += __shfl_xor_sync(0xffffffffu, ps1, 2);
                l0[mt] = l0[mt] * al0 + ps0;
                l1[mt] = l1[mt] * al1 + ps1;

                #pragma unroll
                for (int nt = 0; nt < 8; nt++) {
                    acc[mt][nt][0] *= al0; acc[mt][nt][1] *= al0;
                    acc[mt][nt][2] *= al1; acc[mt][nt][3] *= al1;
                }
            }

            #pragma unroll
            for (int ks = 0; ks < 4; ks++) {
                uint32_t af[2][4];
                #pragma unroll
                for (int mt = 0; mt < 2; mt++) {
                    af[mt][0] = packh2(sf[mt][2 * ks][0],     sf[mt][2 * ks][1]);
                    af[mt][1] = packh2(sf[mt][2 * ks][2],     sf[mt][2 * ks][3]);
                    af[mt][2] = packh2(sf[mt][2 * ks + 1][0], sf[mt][2 * ks + 1][1]);
                    af[mt][3] = packh2(sf[mt][2 * ks + 1][2], sf[mt][2 * ks + 1][3]);
                }
                #pragma unroll
                for (int p = 0; p < 4; p++) {
                    uint32_t vb[4];
                    ldm_x4t(vb, vfrag_base + (uint32_t)(st * FKV_H * 2)
                                + (uint32_t)((ks * 16 * FQSTR + p * 16) << 1));
                    #pragma unroll
                    for (int mt = 0; mt < 2; mt++) {
                        mma16(acc[mt][2 * p],     af[mt], vb);
                        mma16(acc[mt][2 * p + 1], af[mt], vb + 2);
                    }
                }
            }
        }
    }

    #pragma unroll
    for (int mt = 0; mt < 2; mt++) {
        float inv0 = 1.f / l0[mt], inv1 = 1.f / l1[mt];
        size_t r0 = ((size_t)(b * SS + q0 + qb + mt * 16 + g)) * DD + h * DHD;
        size_t r1 = r0 + 8 * DD;
        #pragma unroll
        for (int nt = 0; nt < 8; nt++) {
            int col = nt * 8 + 2 * c;
            *(__half2*)(O + r0 + col) =
                __floats2half2_rn(acc[mt][nt][0] * inv0, acc[mt][nt][1] * inv0);
            *(__half2*)(O + r1 + col) =
                __floats2half2_rn(acc[mt][nt][2] * inv1, acc[mt][nt][3] * inv1);
        }
    }
}

// ---------------- launch ---------------------------------------------------
extern "C" void kernel_launch(void* const* d_in, const int* in_sizes, int n_in,
                              void* d_out, int out_size)
{
    const float* hidden = (const float*)d_in[0];
    const int*   mask   = (const int*)d_in[1];
    const float* wq = (const float*)d_in[2];
    const float* bq = (const float*)d_in[3];
    const float* wk = (const float*)d_in[4];
    const float* bk = (const float*)d_in[5];
    const float* wv = (const float*)d_in[6];
    const float* bv = (const float*)d_in[7];
    const float* wo = (const float*)d_in[8];
    const float* bo = (const float*)d_in[9];
    const float* w1 = (const float*)d_in[10];
    const float* b1 = (const float*)d_in[11];
    const float* w2 = (const float*)d_in[12];
    const float* b2 = (const float*)d_in[13];
    const float* ln1_g = (const float*)d_in[14];
    const float* ln1_b = (const float*)d_in[15];
    const float* ln2_g = (const float*)d_in[16];
    const float* ln2_b = (const float*)d_in[17];
    float* out = (float*)d_out;

    __half *ln, *qkv, *attn, *f1, *wqkvh, *woh, *w1h, *w2h;
    float *h1, *bqkv;
    cudaGetSymbolAddress((void**)&ln,    g_ln);
    cudaGetSymbolAddress((void**)&qkv,   g_qkv);
    cudaGetSymbolAddress((void**)&attn,  g_attn);
    cudaGetSymbolAddress((void**)&h1,    g_h1);
    cudaGetSymbolAddress((void**)&f1,    g_f1);
    cudaGetSymbolAddress((void**)&wqkvh, g_wqkv);
    cudaGetSymbolAddress((void**)&bqkv,  g_bqkv);
    cudaGetSymbolAddress((void**)&woh,   g_wo);
    cudaGetSymbolAddress((void**)&w1h,   g_w1);
    cudaGetSymbolAddress((void**)&w2h,   g_w2);

    cudaFuncSetAttribute(flash_f16,
                         cudaFuncAttributeMaxDynamicSharedMemorySize, FLASH_SMEM);
    cudaFuncSetAttribute(gemm_f16<1>,
                         cudaFuncAttributeMaxDynamicSharedMemorySize, GEMM_SMEM);
    cudaFuncSetAttribute(gemm_f16<2>,
                         cudaFuncAttributeMaxDynamicSharedMemorySize, GEMM_SMEM);
    cudaFuncSetAttribute(gemm_f16<3>,
                         cudaFuncAttributeMaxDynamicSharedMemorySize, GEMM_SMEM);

    // one fused pack launch
    pack_all<<<(unsigned)PACK_BLOCKS, 256>>>(wq, wk, wv, wo, w1, w2, bq, bk, bv,
                                             wqkvh, woh, w1h, w2h, bqkv);

    // 1) LN1 (warp-per-row)
    ln_kernel<<<NROWS / 8, 256>>>(hidden, ln1_g, ln1_b, ln);

    // 2) fused QKV projection -> fp16 (128-thread CTAs)
    dim3 gQKV(NQKV / 128, NROWS / 128);
    gemm_f16<3><<<gQKV, 128, GEMM_SMEM>>>(ln, wqkvh, bqkv, nullptr, qkv,
                                          NROWS, DD, NQKV);

    // 3) attention (4-warp CTA)
    flash_f16<<<dim3(SS / 128, HH, BB), 128, FLASH_SMEM>>>(
        qkv, qkv + DD, qkv + 2 * DD, NQKV, mask, attn);

    // 4) output projection + residual -> fp32
    dim3 gD(DD / 128, NROWS / 128);
    gemm_f16<2><<<gD, 128, GEMM_SMEM>>>(attn, woh, bo, hidden, h1, NROWS, DD, DD);

    // 5) LN2
    ln_kernel<<<NROWS / 8, 256>>>(h1, ln2_g, ln2_b, ln);

    // 6) FFN
    dim3 gF(DFF / 128, NROWS / 128);
    gemm_f16<1><<<gF, 128, GEMM_SMEM>>>(ln, w1h, b1, nullptr, f1, NROWS, DD, DFF);
    gemm_f16<2><<<gD, 128, GEMM_SMEM>>>(f1, w2h, b2, h1, out, NROWS, DFF, DD);
}